// round 4
// baseline (speedup 1.0000x reference)
#include <cuda_runtime.h>
#include <cuda_fp16.h>
#include <cstdint>
#include <math.h>

#define T_TOK 4096
#define H_DIM 2048
#define I_DIM 768
#define E_NUM 8

// ---- scratch (device globals; no allocation allowed) ----
__device__ int    g_cnt[E_NUM];
__device__ int    g_tok[E_NUM * T_TOK];
__device__ float  g_wt [E_NUM * T_TOK];
__device__ __half g_acth[(size_t)E_NUM * T_TOK * I_DIM];
__device__ __half g_actl[(size_t)E_NUM * T_TOK * I_DIM];
__device__ __half g_xh [(size_t)T_TOK * H_DIM];
__device__ __half g_xl [(size_t)T_TOK * H_DIM];
__device__ __half g_w0h[(size_t)E_NUM * H_DIM * I_DIM];
__device__ __half g_w0l[(size_t)E_NUM * H_DIM * I_DIM];
__device__ __half g_w1h[(size_t)E_NUM * H_DIM * I_DIM];
__device__ __half g_w1l[(size_t)E_NUM * H_DIM * I_DIM];
__device__ __half g_woh[(size_t)E_NUM * I_DIM * H_DIM];
__device__ __half g_wol[(size_t)E_NUM * I_DIM * H_DIM];

// ============================ helpers ====================================
__device__ __forceinline__ uint32_t smem_u32(const void* p) {
    uint32_t a;
    asm("{ .reg .u64 t; cvta.to.shared.u64 t, %1; cvt.u32.u64 %0, t; }" : "=r"(a) : "l"(p));
    return a;
}
__device__ __forceinline__ void ldm_x4(uint32_t* r, uint32_t a) {
    asm volatile("ldmatrix.sync.aligned.m8n8.x4.shared.b16 {%0,%1,%2,%3}, [%4];"
                 : "=r"(r[0]), "=r"(r[1]), "=r"(r[2]), "=r"(r[3]) : "r"(a));
}
__device__ __forceinline__ void ldm_x4_t(uint32_t* r, uint32_t a) {
    asm volatile("ldmatrix.sync.aligned.m8n8.x4.trans.shared.b16 {%0,%1,%2,%3}, [%4];"
                 : "=r"(r[0]), "=r"(r[1]), "=r"(r[2]), "=r"(r[3]) : "r"(a));
}
__device__ __forceinline__ void mma16816(float* c, const uint32_t* a, uint32_t b0, uint32_t b1) {
    asm volatile("mma.sync.aligned.m16n8k16.row.col.f32.f16.f16.f32 "
                 "{%0,%1,%2,%3}, {%4,%5,%6,%7}, {%8,%9}, {%0,%1,%2,%3};"
                 : "+f"(c[0]), "+f"(c[1]), "+f"(c[2]), "+f"(c[3])
                 : "r"(a[0]), "r"(a[1]), "r"(a[2]), "r"(a[3]), "r"(b0), "r"(b1));
}
__device__ __forceinline__ void cpa16(uint32_t dst, const void* src, int srcsize) {
    asm volatile("cp.async.cg.shared.global [%0], [%1], 16, %2;"
                 :: "r"(dst), "l"(src), "r"(srcsize) : "memory");
}
#define CP_COMMIT() asm volatile("cp.async.commit_group;" ::: "memory")
#define CP_WAIT1()  asm volatile("cp.async.wait_group 1;" ::: "memory")
#define CP_WAIT0()  asm volatile("cp.async.wait_group 0;" ::: "memory")

// ---------------------------------------------------------------------------
__global__ void k_init() { if (threadIdx.x < E_NUM) g_cnt[threadIdx.x] = 0; }

// fp32 -> hi/lo fp16 planes
__global__ void k_cvt(const float* __restrict__ s, __half* __restrict__ hi,
                      __half* __restrict__ lo, int n4) {
    int i = blockIdx.x * blockDim.x + threadIdx.x;
    if (i >= n4) return;
    float4 v = ((const float4*)s)[i];
    __half h0 = __float2half_rn(v.x), h1 = __float2half_rn(v.y);
    __half h2 = __float2half_rn(v.z), h3 = __float2half_rn(v.w);
    __half l0 = __float2half_rn(v.x - __half2float(h0));
    __half l1 = __float2half_rn(v.y - __half2float(h1));
    __half l2 = __float2half_rn(v.z - __half2float(h2));
    __half l3 = __float2half_rn(v.w - __half2float(h3));
    ((__half2*)hi)[2 * i]     = __halves2half2(h0, h1);
    ((__half2*)hi)[2 * i + 1] = __halves2half2(h2, h3);
    ((__half2*)lo)[2 * i]     = __halves2half2(l0, l1);
    ((__half2*)lo)[2 * i + 1] = __halves2half2(l2, l3);
}

// ---------------------------------------------------------------------------
__global__ void k_router(const float* __restrict__ x, const float* __restrict__ wr,
                         float* __restrict__ out_logits, int write_logits) {
    int warp = threadIdx.x >> 5, lane = threadIdx.x & 31;
    int t = blockIdx.x * 8 + warp;
    if (t >= T_TOK) return;
    float acc[E_NUM];
#pragma unroll
    for (int e = 0; e < E_NUM; e++) acc[e] = 0.f;
    const float* xp = x + (size_t)t * H_DIM;
    for (int h = lane; h < H_DIM; h += 32) {
        float xv = xp[h];
        const float* w = wr + (size_t)h * E_NUM;
#pragma unroll
        for (int e = 0; e < E_NUM; e++) acc[e] += xv * w[e];
    }
#pragma unroll
    for (int e = 0; e < E_NUM; e++)
#pragma unroll
        for (int o = 16; o > 0; o >>= 1)
            acc[e] += __shfl_xor_sync(0xffffffffu, acc[e], o);
    if (lane == 0) {
        if (write_logits)
#pragma unroll
            for (int e = 0; e < E_NUM; e++)
                out_logits[(size_t)t * E_NUM + e] = acc[e];
        int i1 = 0;
#pragma unroll
        for (int e = 1; e < E_NUM; e++) if (acc[e] > acc[i1]) i1 = e;
        int i2 = (i1 == 0) ? 1 : 0;
#pragma unroll
        for (int e = 0; e < E_NUM; e++)
            if (e != i1 && acc[e] > acc[i2]) i2 = e;
        float p2 = expf(acc[i2] - acc[i1]);
        float w1 = 1.f / (1.f + p2), w2 = p2 * w1;
        int p;
        p = atomicAdd(&g_cnt[i1], 1);
        g_tok[i1 * T_TOK + p] = t; g_wt[i1 * T_TOK + p] = w1;
        p = atomicAdd(&g_cnt[i2], 1);
        g_tok[i2 * T_TOK + p] = t; g_wt[i2 * T_TOK + p] = w2;
    }
}

// ---------------------------------------------------------------------------
// Shared GEMM geometry: BM=128, BN=128, BK=16, 256 thr, warps 2(M)x4(N),
// warp tile 64x32. smem/stage: Ah 4K | Al 4K | Bh 4K | Bl 4K. 3 stages.
// A swizzle (32B rows):  off ^ (((row>>2)&1)<<4); B (256B rows): ^((k&7)<<4)
// fp16x3: D += Ah*Bh + Ah*Bl + Al*Bh.

#define COMPUTE_STAGE(SB0)                                                    \
    do {                                                                      \
        uint32_t Af[4][4], Al_[4][4], Bf[2][4], Bl_[2][4];                    \
        _Pragma("unroll")                                                     \
        for (int i = 0; i < 4; i++) {                                         \
            int row = arow_l + i * 16;                                        \
            uint32_t ad = (SB0) + row * 32 +                                  \
                          (acol_l ^ ((((uint32_t)row >> 2) & 1) << 4));       \
            ldm_x4(Af[i], ad);                                                \
            ldm_x4(Al_[i], ad + 4096);                                        \
        }                                                                     \
        _Pragma("unroll")                                                     \
        for (int jj = 0; jj < 2; jj++) {                                      \
            int nat = bnat_l + jj * 2;                                        \
            uint32_t bd = (SB0) + 8192 + bk_l * 256 +                         \
                          ((uint32_t)(nat ^ (bk_l & 7)) << 4);                \
            ldm_x4_t(Bf[jj], bd);                                             \
            ldm_x4_t(Bl_[jj], bd + 4096);                                     \
        }                                                                     \
        _Pragma("unroll")                                                     \
        for (int i = 0; i < 4; i++)                                           \
            _Pragma("unroll")                                                 \
            for (int j = 0; j < 4; j++) {                                     \
                int jj = j >> 1, o = (j & 1) * 2;                             \
                mma16816(c[i][j], Af[i],  Bf[jj][o],  Bf[jj][o + 1]);         \
                mma16816(c[i][j], Af[i],  Bl_[jj][o], Bl_[jj][o + 1]);        \
                mma16816(c[i][j], Al_[i], Bf[jj][o],  Bf[jj][o + 1]);         \
            }                                                                 \
    } while (0)

// GEMM1: per expert, [Ne,H] x [H, 64 gate + 64 up interleaved by 8] -> silu*u
// B tile n8-block j: even = wi0 cols [i0+(j>>1)*8, +8), odd = wi1 same cols.
__global__ __launch_bounds__(256)
void k_mlp1() {
    __shared__ __align__(16) char sm[3][16384];
    int e  = blockIdx.z;
    int ne = g_cnt[e];
    int m0 = blockIdx.x * 128;
    if (m0 >= ne) return;
    int i0 = blockIdx.y * 64;

    int tid = threadIdx.x, lane = tid & 31, wid = tid >> 5;
    int warpM = (wid >> 2) * 64, warpN = (wid & 3) * 32;
    uint32_t sbase = smem_u32(sm);

    // A fill map
    int ar = tid >> 1;
    uint32_t aswz = (uint32_t)(ar * 32) +
                    (((uint32_t)((tid & 1) * 16)) ^ ((((uint32_t)ar >> 2) & 1) << 4));
    int av16 = ((m0 + ar) < ne) ? 16 : 0;
    size_t aoff = 0;
    if (av16) aoff = (size_t)g_tok[e * T_TOK + m0 + ar] * H_DIM + (tid & 1) * 8;
    const __half* ah = g_xh + aoff;
    const __half* al = g_xl + aoff;

    // B fill map: bat even -> wi0, odd -> wi1; cols i0 + (bat>>1)*8
    int bkk = tid & 15, bat = tid >> 4;
    uint32_t bswz = (uint32_t)(bkk * 256) + ((uint32_t)(bat ^ (bkk & 7)) << 4);
    size_t wsel = (size_t)e * H_DIM * I_DIM + (size_t)bkk * I_DIM + i0 + (bat >> 1) * 8;
    const __half* bh = ((bat & 1) ? g_w1h : g_w0h) + wsel;
    const __half* bl = ((bat & 1) ? g_w1l : g_w0l) + wsel;

    float c[4][4][4];
#pragma unroll
    for (int i = 0; i < 4; i++)
#pragma unroll
        for (int j = 0; j < 4; j++)
#pragma unroll
            for (int q = 0; q < 4; q++) c[i][j][q] = 0.f;

#define ISSUE1(S, C) do {                                                    \
    uint32_t s_ = sbase + (S) * 16384;                                       \
    cpa16(s_ + aswz,          ah + (size_t)(C) * 16, av16);                  \
    cpa16(s_ + 4096  + aswz,  al + (size_t)(C) * 16, av16);                  \
    cpa16(s_ + 8192  + bswz,  bh + (size_t)(C) * 16 * I_DIM, 16);            \
    cpa16(s_ + 12288 + bswz,  bl + (size_t)(C) * 16 * I_DIM, 16);            \
    CP_COMMIT();                                                             \
} while (0)

    ISSUE1(0, 0);
    ISSUE1(1, 1);

    int arow_l = warpM + (lane & 15);
    uint32_t acol_l = (uint32_t)((lane >> 4) * 16);
    int bk_l = (lane & 7) + ((lane >> 3) & 1) * 8;
    int bnat_l = (warpN >> 3) + ((lane >> 4) & 1);

    const int NC = H_DIM / 16;  // 128
    for (int cc = 0; cc < NC; cc++) {
        if (cc + 1 < NC) { CP_WAIT1(); } else { CP_WAIT0(); }
        __syncthreads();
        if (cc + 2 < NC) ISSUE1((cc + 2) % 3, cc + 2);
        COMPUTE_STAGE(sbase + (cc % 3) * 16384);
    }
#undef ISSUE1

    // Epilogue: j pairs (0,1),(2,3) = (gate,up) for I cols i0+(warpN>>4+jp)*8+gc
    int gr = lane >> 2, gc = (lane & 3) * 2;
#pragma unroll
    for (int i = 0; i < 4; i++) {
#pragma unroll
        for (int jp = 0; jp < 2; jp++) {
            int jg = jp * 2, ju = jp * 2 + 1;
            int ic = i0 + ((warpN >> 4) + jp) * 8 + gc;
#pragma unroll
            for (int hf = 0; hf < 2; hf++) {
                int slot = m0 + warpM + i * 16 + gr + hf * 8;
                if (slot < ne) {
                    float g0 = c[i][jg][2 * hf], g1 = c[i][jg][2 * hf + 1];
                    float u0 = c[i][ju][2 * hf], u1 = c[i][ju][2 * hf + 1];
                    float a0 = (g0 / (1.f + expf(-g0))) * u0;
                    float a1 = (g1 / (1.f + expf(-g1))) * u1;
                    __half h0 = __float2half_rn(a0), h1 = __float2half_rn(a1);
                    __half l0 = __float2half_rn(a0 - __half2float(h0));
                    __half l1 = __float2half_rn(a1 - __half2float(h1));
                    size_t off = ((size_t)e * T_TOK + slot) * I_DIM + ic;
                    *(__half2*)(g_acth + off) = __halves2half2(h0, h1);
                    *(__half2*)(g_actl + off) = __halves2half2(l0, l1);
                }
            }
        }
    }
}

// ---------------------------------------------------------------------------
__global__ __launch_bounds__(256)
void k_mlp2(float* __restrict__ out) {
    __shared__ __align__(16) char sm[3][16384];
    int e  = blockIdx.z;
    int ne = g_cnt[e];
    int m0 = blockIdx.x * 128;
    if (m0 >= ne) return;
    int n0 = blockIdx.y * 128;

    int tid = threadIdx.x, lane = tid & 31, wid = tid >> 5;
    int warpM = (wid >> 2) * 64, warpN = (wid & 3) * 32;
    uint32_t sbase = smem_u32(sm);

    int ar = tid >> 1;
    uint32_t aswz = (uint32_t)(ar * 32) +
                    (((uint32_t)((tid & 1) * 16)) ^ ((((uint32_t)ar >> 2) & 1) << 4));
    int av16 = ((m0 + ar) < ne) ? 16 : 0;
    size_t aoff = ((size_t)e * T_TOK + m0 + ar) * I_DIM + (tid & 1) * 8;
    const __half* ah = g_acth + aoff;
    const __half* al = g_actl + aoff;

    int bkk = tid & 15, bat = tid >> 4;
    uint32_t bswz = (uint32_t)(bkk * 256) + ((uint32_t)(bat ^ (bkk & 7)) << 4);
    size_t boff = (size_t)e * I_DIM * H_DIM + (size_t)bkk * H_DIM + n0 + bat * 8;
    const __half* bh = g_woh + boff;
    const __half* bl = g_wol + boff;

    float c[4][4][4];
#pragma unroll
    for (int i = 0; i < 4; i++)
#pragma unroll
        for (int j = 0; j < 4; j++)
#pragma unroll
            for (int q = 0; q < 4; q++) c[i][j][q] = 0.f;

#define ISSUE2(S, C) do {                                                    \
    uint32_t s_ = sbase + (S) * 16384;                                       \
    cpa16(s_ + aswz,          ah + (size_t)(C) * 16, av16);                  \
    cpa16(s_ + 4096  + aswz,  al + (size_t)(C) * 16, av16);                  \
    cpa16(s_ + 8192  + bswz,  bh + (size_t)(C) * 16 * H_DIM, 16);            \
    cpa16(s_ + 12288 + bswz,  bl + (size_t)(C) * 16 * H_DIM, 16);            \
    CP_COMMIT();                                                             \
} while (0)

    ISSUE2(0, 0);
    ISSUE2(1, 1);

    int arow_l = warpM + (lane & 15);
    uint32_t acol_l = (uint32_t)((lane >> 4) * 16);
    int bk_l = (lane & 7) + ((lane >> 3) & 1) * 8;
    int bnat_l = (warpN >> 3) + ((lane >> 4) & 1);

    const int NC = I_DIM / 16;  // 48
    for (int cc = 0; cc < NC; cc++) {
        if (cc + 1 < NC) { CP_WAIT1(); } else { CP_WAIT0(); }
        __syncthreads();
        if (cc + 2 < NC) ISSUE2((cc + 2) % 3, cc + 2);
        COMPUTE_STAGE(sbase + (cc % 3) * 16384);
    }
#undef ISSUE2

    int gr = lane >> 2, gc = (lane & 3) * 2;
#pragma unroll
    for (int i = 0; i < 4; i++) {
#pragma unroll
        for (int hf = 0; hf < 2; hf++) {
            int r = m0 + warpM + i * 16 + gr + hf * 8;
            if (r < ne) {
                int   t = g_tok[e * T_TOK + r];
                float w = g_wt [e * T_TOK + r];
                float* op = out + (size_t)t * H_DIM + n0 + warpN;
#pragma unroll
                for (int j = 0; j < 4; j++) {
                    atomicAdd(op + j * 8 + gc,     w * c[i][j][2 * hf]);
                    atomicAdd(op + j * 8 + gc + 1, w * c[i][j][2 * hf + 1]);
                }
            }
        }
    }
}

// ---------------------------------------------------------------------------
extern "C" void kernel_launch(void* const* d_in, const int* in_sizes, int n_in,
                              void* d_out, int out_size) {
    const float* x   = (const float*)d_in[0];
    const float* wr  = (const float*)d_in[1];
    const float* wi0 = (const float*)d_in[2];
    const float* wi1 = (const float*)d_in[3];
    const float* wo  = (const float*)d_in[4];
    float* out = (float*)d_out;

    int write_logits = (out_size >= T_TOK * H_DIM + T_TOK * E_NUM) ? 1 : 0;

    cudaMemsetAsync(out, 0, (size_t)T_TOK * H_DIM * sizeof(float));
    k_init<<<1, 32>>>();
    k_router<<<T_TOK / 8, 256>>>(x, wr, out + (size_t)T_TOK * H_DIM, write_logits);

    {
        __half *xh, *xl, *w0h, *w0l, *w1h, *w1l, *woh, *wol;
        cudaGetSymbolAddress((void**)&xh,  g_xh);  cudaGetSymbolAddress((void**)&xl,  g_xl);
        cudaGetSymbolAddress((void**)&w0h, g_w0h); cudaGetSymbolAddress((void**)&w0l, g_w0l);
        cudaGetSymbolAddress((void**)&w1h, g_w1h); cudaGetSymbolAddress((void**)&w1l, g_w1l);
        cudaGetSymbolAddress((void**)&woh, g_woh); cudaGetSymbolAddress((void**)&wol, g_wol);
        int nx = T_TOK * H_DIM / 4;
        int nw = E_NUM * H_DIM * I_DIM / 4;
        k_cvt<<<(nx + 255) / 256, 256>>>(x,   xh,  xl,  nx);
        k_cvt<<<(nw + 255) / 256, 256>>>(wi0, w0h, w0l, nw);
        k_cvt<<<(nw + 255) / 256, 256>>>(wi1, w1h, w1l, nw);
        k_cvt<<<(nw + 255) / 256, 256>>>(wo,  woh, wol, nw);
    }

    dim3 g1(T_TOK / 128, I_DIM / 64, E_NUM);   // (32, 12, 8)
    k_mlp1<<<g1, 256>>>();

    dim3 g2(T_TOK / 128, H_DIM / 128, E_NUM);  // (32, 16, 8)
    k_mlp2<<<g2, 256>>>(out);
}

// round 5
// speedup vs baseline: 1.1280x; 1.1280x over previous
#include <cuda_runtime.h>
#include <cuda_fp16.h>
#include <cstdint>
#include <math.h>

#define T_TOK 4096
#define H_DIM 2048
#define I_DIM 768
#define E_NUM 8

// ---- scratch (device globals; no allocation allowed) ----
__device__ int    g_cnt[E_NUM];
__device__ int    g_tok[E_NUM * T_TOK];
__device__ float  g_wt [E_NUM * T_TOK];
__device__ __half g_acth[(size_t)E_NUM * T_TOK * I_DIM];
__device__ __half g_actl[(size_t)E_NUM * T_TOK * I_DIM];
__device__ __half g_xh [(size_t)T_TOK * H_DIM];
__device__ __half g_xl [(size_t)T_TOK * H_DIM];
__device__ __half g_w0h[(size_t)E_NUM * H_DIM * I_DIM];
__device__ __half g_w0l[(size_t)E_NUM * H_DIM * I_DIM];
__device__ __half g_w1h[(size_t)E_NUM * H_DIM * I_DIM];
__device__ __half g_w1l[(size_t)E_NUM * H_DIM * I_DIM];
__device__ __half g_woh[(size_t)E_NUM * I_DIM * H_DIM];
__device__ __half g_wol[(size_t)E_NUM * I_DIM * H_DIM];

// ============================ helpers ====================================
__device__ __forceinline__ uint32_t smem_u32(const void* p) {
    uint32_t a;
    asm("{ .reg .u64 t; cvta.to.shared.u64 t, %1; cvt.u32.u64 %0, t; }" : "=r"(a) : "l"(p));
    return a;
}
__device__ __forceinline__ void ldm_x4(uint32_t* r, uint32_t a) {
    asm volatile("ldmatrix.sync.aligned.m8n8.x4.shared.b16 {%0,%1,%2,%3}, [%4];"
                 : "=r"(r[0]), "=r"(r[1]), "=r"(r[2]), "=r"(r[3]) : "r"(a));
}
__device__ __forceinline__ void ldm_x4_t(uint32_t* r, uint32_t a) {
    asm volatile("ldmatrix.sync.aligned.m8n8.x4.trans.shared.b16 {%0,%1,%2,%3}, [%4];"
                 : "=r"(r[0]), "=r"(r[1]), "=r"(r[2]), "=r"(r[3]) : "r"(a));
}
__device__ __forceinline__ void mma16816(float* c, const uint32_t* a, uint32_t b0, uint32_t b1) {
    asm volatile("mma.sync.aligned.m16n8k16.row.col.f32.f16.f16.f32 "
                 "{%0,%1,%2,%3}, {%4,%5,%6,%7}, {%8,%9}, {%0,%1,%2,%3};"
                 : "+f"(c[0]), "+f"(c[1]), "+f"(c[2]), "+f"(c[3])
                 : "r"(a[0]), "r"(a[1]), "r"(a[2]), "r"(a[3]), "r"(b0), "r"(b1));
}

// ---------------------------------------------------------------------------
__global__ void k_init() { if (threadIdx.x < E_NUM) g_cnt[threadIdx.x] = 0; }

// fp32 -> hi/lo fp16 planes; handles two tensors per launch.
__global__ void k_cvt2(const float* __restrict__ s0, __half* __restrict__ h0,
                       __half* __restrict__ l0, int n0,
                       const float* __restrict__ s1, __half* __restrict__ h1,
                       __half* __restrict__ l1, int n1) {
    int i = blockIdx.x * blockDim.x + threadIdx.x;
    const float* s; __half* hh; __half* ll; int j;
    if (i < n0)           { s = s0; hh = h0; ll = l0; j = i; }
    else if (i < n0 + n1) { s = s1; hh = h1; ll = l1; j = i - n0; }
    else return;
    float4 v = ((const float4*)s)[j];
    __half a0 = __float2half_rn(v.x), a1 = __float2half_rn(v.y);
    __half a2 = __float2half_rn(v.z), a3 = __float2half_rn(v.w);
    __half b0 = __float2half_rn(v.x - __half2float(a0));
    __half b1 = __float2half_rn(v.y - __half2float(a1));
    __half b2 = __float2half_rn(v.z - __half2float(a2));
    __half b3 = __float2half_rn(v.w - __half2float(a3));
    ((__half2*)hh)[2 * j]     = __halves2half2(a0, a1);
    ((__half2*)hh)[2 * j + 1] = __halves2half2(a2, a3);
    ((__half2*)ll)[2 * j]     = __halves2half2(b0, b1);
    ((__half2*)ll)[2 * j + 1] = __halves2half2(b2, b3);
}

// ---------------------------------------------------------------------------
__global__ void k_router(const float* __restrict__ x, const float* __restrict__ wr,
                         float* __restrict__ out_logits, int write_logits) {
    int warp = threadIdx.x >> 5, lane = threadIdx.x & 31;
    int t = blockIdx.x * 8 + warp;
    if (t >= T_TOK) return;
    float acc[E_NUM];
#pragma unroll
    for (int e = 0; e < E_NUM; e++) acc[e] = 0.f;
    const float* xp = x + (size_t)t * H_DIM;
    for (int h = lane; h < H_DIM; h += 32) {
        float xv = xp[h];
        const float* w = wr + (size_t)h * E_NUM;
#pragma unroll
        for (int e = 0; e < E_NUM; e++) acc[e] += xv * w[e];
    }
#pragma unroll
    for (int e = 0; e < E_NUM; e++)
#pragma unroll
        for (int o = 16; o > 0; o >>= 1)
            acc[e] += __shfl_xor_sync(0xffffffffu, acc[e], o);
    if (lane == 0) {
        if (write_logits)
#pragma unroll
            for (int e = 0; e < E_NUM; e++)
                out_logits[(size_t)t * E_NUM + e] = acc[e];
        int i1 = 0;
#pragma unroll
        for (int e = 1; e < E_NUM; e++) if (acc[e] > acc[i1]) i1 = e;
        int i2 = (i1 == 0) ? 1 : 0;
#pragma unroll
        for (int e = 0; e < E_NUM; e++)
            if (e != i1 && acc[e] > acc[i2]) i2 = e;
        float p2 = expf(acc[i2] - acc[i1]);
        float w1 = 1.f / (1.f + p2), w2 = p2 * w1;
        int p;
        p = atomicAdd(&g_cnt[i1], 1);
        g_tok[i1 * T_TOK + p] = t; g_wt[i1 * T_TOK + p] = w1;
        p = atomicAdd(&g_cnt[i2], 1);
        g_tok[i2 * T_TOK + p] = t; g_wt[i2 * T_TOK + p] = w2;
    }
}

// ---------------------------------------------------------------------------
// GEMM geometry: BM=128, BN=128, BK=16, 256 thr, warps 2(M)x4(N), warp 64x32.
// smem/buffer: Ah 4K | Al 4K | Bh 4K | Bl 4K; 2 buffers, register prefetch.
// A swizzle (32B rows): off ^ (((row>>2)&1)<<4); B (256B rows): ^((k&7)<<4)
// fp16x3: D += Ah*Bh + Ah*Bl + Al*Bh.

#define COMPUTE_STAGE(SB0)                                                    \
    do {                                                                      \
        uint32_t Af[4][4], Al_[4][4], Bf[2][4], Bl_[2][4];                    \
        _Pragma("unroll")                                                     \
        for (int i = 0; i < 4; i++) {                                         \
            int row = arow_l + i * 16;                                        \
            uint32_t ad = (SB0) + row * 32 +                                  \
                          (acol_l ^ ((((uint32_t)row >> 2) & 1) << 4));       \
            ldm_x4(Af[i], ad);                                                \
            ldm_x4(Al_[i], ad + 4096);                                        \
        }                                                                     \
        _Pragma("unroll")                                                     \
        for (int jj = 0; jj < 2; jj++) {                                      \
            int nat = bnat_l + jj * 2;                                        \
            uint32_t bd = (SB0) + 8192 + bk_l * 256 +                         \
                          ((uint32_t)(nat ^ (bk_l & 7)) << 4);                \
            ldm_x4_t(Bf[jj], bd);                                             \
            ldm_x4_t(Bl_[jj], bd + 4096);                                     \
        }                                                                     \
        _Pragma("unroll")                                                     \
        for (int i = 0; i < 4; i++)                                           \
            _Pragma("unroll")                                                 \
            for (int j = 0; j < 4; j++) {                                     \
                int jj = j >> 1, o = (j & 1) * 2;                             \
                mma16816(c[i][j], Af[i],  Bf[jj][o],  Bf[jj][o + 1]);         \
                mma16816(c[i][j], Af[i],  Bl_[jj][o], Bl_[jj][o + 1]);        \
                mma16816(c[i][j], Al_[i], Bf[jj][o],  Bf[jj][o + 1]);         \
            }                                                                 \
    } while (0)

// GEMM1: per expert, [Ne,H] x [H, 64 gate + 64 up interleaved by 8] -> silu*u
// B tile n8-block j: even = wi0 cols [i0+(j>>1)*8, +8), odd = wi1 same cols.
__global__ __launch_bounds__(256)
void k_mlp1() {
    __shared__ __align__(16) char sm[2][16384];
    int e  = blockIdx.z;
    int ne = g_cnt[e];
    int m0 = blockIdx.x * 128;
    if (m0 >= ne) return;
    int i0 = blockIdx.y * 64;

    int tid = threadIdx.x, lane = tid & 31, wid = tid >> 5;
    int warpM = (wid >> 2) * 64, warpN = (wid & 3) * 32;
    uint32_t sbase = smem_u32(sm);

    // A fill map (gathered token rows)
    int ar = tid >> 1;
    uint32_t aswz = (uint32_t)(ar * 32) +
                    (((uint32_t)((tid & 1) * 16)) ^ ((((uint32_t)ar >> 2) & 1) << 4));
    bool av = (m0 + ar) < ne;
    size_t aoff = 0;
    if (av) aoff = (size_t)g_tok[e * T_TOK + m0 + ar] * H_DIM + (tid & 1) * 8;
    const __half* ah = g_xh + aoff;
    const __half* al = g_xl + aoff;

    // B fill map: bat even -> wi0, odd -> wi1; cols i0 + (bat>>1)*8
    int bkk = tid & 15, bat = tid >> 4;
    uint32_t bswz = (uint32_t)(bkk * 256) + ((uint32_t)(bat ^ (bkk & 7)) << 4);
    size_t wsel = (size_t)e * H_DIM * I_DIM + (size_t)bkk * I_DIM + i0 + (bat >> 1) * 8;
    const __half* bh = ((bat & 1) ? g_w1h : g_w0h) + wsel;
    const __half* bl = ((bat & 1) ? g_w1l : g_w0l) + wsel;

    float c[4][4][4];
#pragma unroll
    for (int i = 0; i < 4; i++)
#pragma unroll
        for (int j = 0; j < 4; j++)
#pragma unroll
            for (int q = 0; q < 4; q++) c[i][j][q] = 0.f;

    uint4 pah, pal, pbh, pbl;
#define LDG1(K0) do {                                                        \
    if (av) { pah = *(const uint4*)(ah + (size_t)(K0));                      \
              pal = *(const uint4*)(al + (size_t)(K0)); }                    \
    else { pah = make_uint4(0,0,0,0); pal = make_uint4(0,0,0,0); }           \
    pbh = *(const uint4*)(bh + (size_t)(K0) * I_DIM);                        \
    pbl = *(const uint4*)(bl + (size_t)(K0) * I_DIM);                        \
} while (0)
#define STS1(BUF) do {                                                       \
    char* s_ = sm[BUF];                                                      \
    *(uint4*)(s_ + aswz)          = pah;                                     \
    *(uint4*)(s_ + 4096  + aswz)  = pal;                                     \
    *(uint4*)(s_ + 8192  + bswz)  = pbh;                                     \
    *(uint4*)(s_ + 12288 + bswz)  = pbl;                                     \
} while (0)

    LDG1(0); STS1(0); __syncthreads();

    int arow_l = warpM + (lane & 15);
    uint32_t acol_l = (uint32_t)((lane >> 4) * 16);
    int bk_l = (lane & 7) + ((lane >> 3) & 1) * 8;
    int bnat_l = (warpN >> 3) + ((lane >> 4) & 1);

    const int NC = H_DIM / 16;  // 128
    for (int cc = 0; cc < NC; cc++) {
        int cur = cc & 1;
        bool more = (cc + 1) < NC;
        if (more) LDG1((cc + 1) * 16);
        COMPUTE_STAGE(sbase + cur * 16384);
        if (more) { __syncthreads(); STS1(cur ^ 1); __syncthreads(); }
    }
#undef LDG1
#undef STS1

    // Epilogue: j pairs (0,1),(2,3) = (gate,up); silu in regs, hi/lo fp16 out.
    int gr = lane >> 2, gc = (lane & 3) * 2;
#pragma unroll
    for (int i = 0; i < 4; i++) {
#pragma unroll
        for (int jp = 0; jp < 2; jp++) {
            int jg = jp * 2, ju = jp * 2 + 1;
            int ic = i0 + ((warpN >> 4) + jp) * 8 + gc;
#pragma unroll
            for (int hf = 0; hf < 2; hf++) {
                int slot = m0 + warpM + i * 16 + gr + hf * 8;
                if (slot < ne) {
                    float g0 = c[i][jg][2 * hf], g1 = c[i][jg][2 * hf + 1];
                    float u0 = c[i][ju][2 * hf], u1 = c[i][ju][2 * hf + 1];
                    float a0 = (g0 / (1.f + expf(-g0))) * u0;
                    float a1 = (g1 / (1.f + expf(-g1))) * u1;
                    __half h0 = __float2half_rn(a0), h1 = __float2half_rn(a1);
                    __half l0 = __float2half_rn(a0 - __half2float(h0));
                    __half l1 = __float2half_rn(a1 - __half2float(h1));
                    size_t off = ((size_t)e * T_TOK + slot) * I_DIM + ic;
                    *(__half2*)(g_acth + off) = __halves2half2(h0, h1);
                    *(__half2*)(g_actl + off) = __halves2half2(l0, l1);
                }
            }
        }
    }
}

// ---------------------------------------------------------------------------
__global__ __launch_bounds__(256)
void k_mlp2(float* __restrict__ out) {
    __shared__ __align__(16) char sm[2][16384];
    int e  = blockIdx.z;
    int ne = g_cnt[e];
    int m0 = blockIdx.x * 128;
    if (m0 >= ne) return;
    int n0 = blockIdx.y * 128;

    int tid = threadIdx.x, lane = tid & 31, wid = tid >> 5;
    int warpM = (wid >> 2) * 64, warpN = (wid & 3) * 32;
    uint32_t sbase = smem_u32(sm);

    int ar = tid >> 1;
    uint32_t aswz = (uint32_t)(ar * 32) +
                    (((uint32_t)((tid & 1) * 16)) ^ ((((uint32_t)ar >> 2) & 1) << 4));
    bool av = (m0 + ar) < ne;
    size_t aoff = ((size_t)e * T_TOK + m0 + ar) * I_DIM + (tid & 1) * 8;
    const __half* ah = g_acth + aoff;
    const __half* al = g_actl + aoff;

    int bkk = tid & 15, bat = tid >> 4;
    uint32_t bswz = (uint32_t)(bkk * 256) + ((uint32_t)(bat ^ (bkk & 7)) << 4);
    size_t boff = (size_t)e * I_DIM * H_DIM + (size_t)bkk * H_DIM + n0 + bat * 8;
    const __half* bh = g_woh + boff;
    const __half* bl = g_wol + boff;

    float c[4][4][4];
#pragma unroll
    for (int i = 0; i < 4; i++)
#pragma unroll
        for (int j = 0; j < 4; j++)
#pragma unroll
            for (int q = 0; q < 4; q++) c[i][j][q] = 0.f;

    uint4 pah, pal, pbh, pbl;
#define LDG2(K0) do {                                                        \
    if (av) { pah = *(const uint4*)(ah + (size_t)(K0));                      \
              pal = *(const uint4*)(al + (size_t)(K0)); }                    \
    else { pah = make_uint4(0,0,0,0); pal = make_uint4(0,0,0,0); }           \
    pbh = *(const uint4*)(bh + (size_t)(K0) * H_DIM);                        \
    pbl = *(const uint4*)(bl + (size_t)(K0) * H_DIM);                        \
} while (0)
#define STS2(BUF) do {                                                       \
    char* s_ = sm[BUF];                                                      \
    *(uint4*)(s_ + aswz)          = pah;                                     \
    *(uint4*)(s_ + 4096  + aswz)  = pal;                                     \
    *(uint4*)(s_ + 8192  + bswz)  = pbh;                                     \
    *(uint4*)(s_ + 12288 + bswz)  = pbl;                                     \
} while (0)

    LDG2(0); STS2(0); __syncthreads();

    int arow_l = warpM + (lane & 15);
    uint32_t acol_l = (uint32_t)((lane >> 4) * 16);
    int bk_l = (lane & 7) + ((lane >> 3) & 1) * 8;
    int bnat_l = (warpN >> 3) + ((lane >> 4) & 1);

    const int NC = I_DIM / 16;  // 48
    for (int cc = 0; cc < NC; cc++) {
        int cur = cc & 1;
        bool more = (cc + 1) < NC;
        if (more) LDG2((cc + 1) * 16);
        COMPUTE_STAGE(sbase + cur * 16384);
        if (more) { __syncthreads(); STS2(cur ^ 1); __syncthreads(); }
    }
#undef LDG2
#undef STS2

    int gr = lane >> 2, gc = (lane & 3) * 2;
#pragma unroll
    for (int i = 0; i < 4; i++) {
#pragma unroll
        for (int hf = 0; hf < 2; hf++) {
            int r = m0 + warpM + i * 16 + gr + hf * 8;
            if (r < ne) {
                int   t = g_tok[e * T_TOK + r];
                float w = g_wt [e * T_TOK + r];
                float* op = out + (size_t)t * H_DIM + n0 + warpN;
#pragma unroll
                for (int j = 0; j < 4; j++) {
                    atomicAdd(op + j * 8 + gc,     w * c[i][j][2 * hf]);
                    atomicAdd(op + j * 8 + gc + 1, w * c[i][j][2 * hf + 1]);
                }
            }
        }
    }
}

// ---------------------------------------------------------------------------
extern "C" void kernel_launch(void* const* d_in, const int* in_sizes, int n_in,
                              void* d_out, int out_size) {
    const float* x   = (const float*)d_in[0];
    const float* wr  = (const float*)d_in[1];
    const float* wi0 = (const float*)d_in[2];
    const float* wi1 = (const float*)d_in[3];
    const float* wo  = (const float*)d_in[4];
    float* out = (float*)d_out;

    int write_logits = (out_size >= T_TOK * H_DIM + T_TOK * E_NUM) ? 1 : 0;

    cudaMemsetAsync(out, 0, (size_t)T_TOK * H_DIM * sizeof(float));
    k_init<<<1, 32>>>();
    k_router<<<T_TOK / 8, 256>>>(x, wr, out + (size_t)T_TOK * H_DIM, write_logits);

    {
        __half *xh, *xl, *w0h, *w0l, *w1h, *w1l, *woh, *wol;
        cudaGetSymbolAddress((void**)&xh,  g_xh);  cudaGetSymbolAddress((void**)&xl,  g_xl);
        cudaGetSymbolAddress((void**)&w0h, g_w0h); cudaGetSymbolAddress((void**)&w0l, g_w0l);
        cudaGetSymbolAddress((void**)&w1h, g_w1h); cudaGetSymbolAddress((void**)&w1l, g_w1l);
        cudaGetSymbolAddress((void**)&woh, g_woh); cudaGetSymbolAddress((void**)&wol, g_wol);
        int nx = T_TOK * H_DIM / 4;
        int nw = E_NUM * H_DIM * I_DIM / 4;
        k_cvt2<<<(nx + nw + 255) / 256, 256>>>(x,   xh,  xl,  nx, wi0, w0h, w0l, nw);
        k_cvt2<<<(nw + nw + 255) / 256, 256>>>(wi1, w1h, w1l, nw, wo,  woh, wol, nw);
    }

    dim3 g1(T_TOK / 128, I_DIM / 64, E_NUM);   // (32, 12, 8)
    k_mlp1<<<g1, 256>>>();

    dim3 g2(T_TOK / 128, H_DIM / 128, E_NUM);  // (32, 16, 8)
    k_mlp2<<<g2, 256>>>(out);
}

// round 6
// speedup vs baseline: 1.2044x; 1.0678x over previous
#include <cuda_runtime.h>
#include <cuda_fp16.h>
#include <cstdint>
#include <math.h>

#define T_TOK 4096
#define H_DIM 2048
#define I_DIM 768
#define E_NUM 8

// ---- scratch (device globals; no allocation allowed) ----
__device__ int    g_cnt[E_NUM];
__device__ int    g_tok[E_NUM * T_TOK];
__device__ float  g_wt [E_NUM * T_TOK];
__device__ __half g_acth[(size_t)E_NUM * T_TOK * I_DIM];
__device__ __half g_actl[(size_t)E_NUM * T_TOK * I_DIM];

// ============================ helpers ====================================
__device__ __forceinline__ uint32_t smem_u32(const void* p) {
    uint32_t a;
    asm("{ .reg .u64 t; cvta.to.shared.u64 t, %1; cvt.u32.u64 %0, t; }" : "=r"(a) : "l"(p));
    return a;
}
__device__ __forceinline__ void ldm_x4(uint32_t* r, uint32_t a) {
    asm volatile("ldmatrix.sync.aligned.m8n8.x4.shared.b16 {%0,%1,%2,%3}, [%4];"
                 : "=r"(r[0]), "=r"(r[1]), "=r"(r[2]), "=r"(r[3]) : "r"(a));
}
__device__ __forceinline__ void ldm_x4_t(uint32_t* r, uint32_t a) {
    asm volatile("ldmatrix.sync.aligned.m8n8.x4.trans.shared.b16 {%0,%1,%2,%3}, [%4];"
                 : "=r"(r[0]), "=r"(r[1]), "=r"(r[2]), "=r"(r[3]) : "r"(a));
}
__device__ __forceinline__ void mma16816(float* c, const uint32_t* a, uint32_t b0, uint32_t b1) {
    asm volatile("mma.sync.aligned.m16n8k16.row.col.f32.f16.f16.f32 "
                 "{%0,%1,%2,%3}, {%4,%5,%6,%7}, {%8,%9}, {%0,%1,%2,%3};"
                 : "+f"(c[0]), "+f"(c[1]), "+f"(c[2]), "+f"(c[3])
                 : "r"(a[0]), "r"(a[1]), "r"(a[2]), "r"(a[3]), "r"(b0), "r"(b1));
}
// split two floats -> packed hi half2 and lo half2 (as u32)
__device__ __forceinline__ void split2(float x, float y, uint32_t& H, uint32_t& L) {
    __half hx = __float2half_rn(x), hy = __float2half_rn(y);
    __half lx = __float2half_rn(x - __half2float(hx));
    __half ly = __float2half_rn(y - __half2float(hy));
    __half2 hh = __halves2half2(hx, hy);
    __half2 ll = __halves2half2(lx, ly);
    H = *(uint32_t*)&hh;
    L = *(uint32_t*)&ll;
}
// split 8 floats (two float4) -> 16B hi vector + 16B lo vector
__device__ __forceinline__ void split8(float4 a, float4 b, uint4& H, uint4& L) {
    split2(a.x, a.y, H.x, L.x);
    split2(a.z, a.w, H.y, L.y);
    split2(b.x, b.y, H.z, L.z);
    split2(b.z, b.w, H.w, L.w);
}

// ---------------------------------------------------------------------------
__global__ void k_init() { if (threadIdx.x < E_NUM) g_cnt[threadIdx.x] = 0; }

// ---------------------------------------------------------------------------
__global__ void k_router(const float* __restrict__ x, const float* __restrict__ wr,
                         float* __restrict__ out_logits, int write_logits) {
    int warp = threadIdx.x >> 5, lane = threadIdx.x & 31;
    int t = blockIdx.x * 8 + warp;
    if (t >= T_TOK) return;
    float acc[E_NUM];
#pragma unroll
    for (int e = 0; e < E_NUM; e++) acc[e] = 0.f;
    const float* xp = x + (size_t)t * H_DIM;
    for (int h = lane; h < H_DIM; h += 32) {
        float xv = xp[h];
        const float* w = wr + (size_t)h * E_NUM;
#pragma unroll
        for (int e = 0; e < E_NUM; e++) acc[e] += xv * w[e];
    }
#pragma unroll
    for (int e = 0; e < E_NUM; e++)
#pragma unroll
        for (int o = 16; o > 0; o >>= 1)
            acc[e] += __shfl_xor_sync(0xffffffffu, acc[e], o);
    if (lane == 0) {
        if (write_logits)
#pragma unroll
            for (int e = 0; e < E_NUM; e++)
                out_logits[(size_t)t * E_NUM + e] = acc[e];
        int i1 = 0;
#pragma unroll
        for (int e = 1; e < E_NUM; e++) if (acc[e] > acc[i1]) i1 = e;
        int i2 = (i1 == 0) ? 1 : 0;
#pragma unroll
        for (int e = 0; e < E_NUM; e++)
            if (e != i1 && acc[e] > acc[i2]) i2 = e;
        float p2 = expf(acc[i2] - acc[i1]);
        float w1 = 1.f / (1.f + p2), w2 = p2 * w1;
        int p;
        p = atomicAdd(&g_cnt[i1], 1);
        g_tok[i1 * T_TOK + p] = t; g_wt[i1 * T_TOK + p] = w1;
        p = atomicAdd(&g_cnt[i2], 1);
        g_tok[i2 * T_TOK + p] = t; g_wt[i2 * T_TOK + p] = w2;
    }
}

// ---------------------------------------------------------------------------
// GEMM geometry: BM=128, BN=128, BK=16, 256 thr, warps 2(M)x4(N), warp 64x32.
// smem/stage: Ah 4K | Al 4K | Bh 4K | Bl 4K; 3 stages, 1 sync/iter.
// A swizzle (32B rows): off ^ (((row>>2)&1)<<4); B (256B rows): ^((k&7)<<4)
// fp16x3: D += Ah*Bh + Ah*Bl + Al*Bh. fp32 operands split to hi/lo at fill.

#define COMPUTE_STAGE(SB0)                                                    \
    do {                                                                      \
        uint32_t Af[4][4], Al_[4][4], Bf[2][4], Bl_[2][4];                    \
        _Pragma("unroll")                                                     \
        for (int i = 0; i < 4; i++) {                                         \
            int row = arow_l + i * 16;                                        \
            uint32_t ad = (SB0) + row * 32 +                                  \
                          (acol_l ^ ((((uint32_t)row >> 2) & 1) << 4));       \
            ldm_x4(Af[i], ad);                                                \
            ldm_x4(Al_[i], ad + 4096);                                        \
        }                                                                     \
        _Pragma("unroll")                                                     \
        for (int jj = 0; jj < 2; jj++) {                                      \
            int nat = bnat_l + jj * 2;                                        \
            uint32_t bd = (SB0) + 8192 + bk_l * 256 +                         \
                          ((uint32_t)(nat ^ (bk_l & 7)) << 4);                \
            ldm_x4_t(Bf[jj], bd);                                             \
            ldm_x4_t(Bl_[jj], bd + 4096);                                     \
        }                                                                     \
        _Pragma("unroll")                                                     \
        for (int i = 0; i < 4; i++)                                           \
            _Pragma("unroll")                                                 \
            for (int j = 0; j < 4; j++) {                                     \
                int jj = j >> 1, o = (j & 1) * 2;                             \
                mma16816(c[i][j], Af[i],  Bf[jj][o],  Bf[jj][o + 1]);         \
                mma16816(c[i][j], Af[i],  Bl_[jj][o], Bl_[jj][o + 1]);        \
                mma16816(c[i][j], Al_[i], Bf[jj][o],  Bf[jj][o + 1]);         \
            }                                                                 \
    } while (0)

// GEMM1: per expert, [Ne,H] x [H, 64 gate + 64 up interleaved by 8] -> silu*u
__global__ __launch_bounds__(256)
void k_mlp1(const float* __restrict__ x,
            const float* __restrict__ wi0, const float* __restrict__ wi1) {
    __shared__ __align__(16) char sm[3][16384];
    int e  = blockIdx.z;
    int ne = g_cnt[e];
    int m0 = blockIdx.x * 128;
    if (m0 >= ne) return;
    int i0 = blockIdx.y * 64;

    int tid = threadIdx.x, lane = tid & 31, wid = tid >> 5;
    int warpM = (wid >> 2) * 64, warpN = (wid & 3) * 32;
    uint32_t sbase = smem_u32(sm);

    // A fill map (gathered token rows, fp32 source)
    int ar = tid >> 1;
    uint32_t aswz = (uint32_t)(ar * 32) +
                    (((uint32_t)((tid & 1) * 16)) ^ ((((uint32_t)ar >> 2) & 1) << 4));
    bool av = (m0 + ar) < ne;
    const float* axp = x;
    if (av) axp = x + (size_t)g_tok[e * T_TOK + m0 + ar] * H_DIM + (tid & 1) * 8;

    // B fill map: bat even -> wi0, odd -> wi1; cols i0 + (bat>>1)*8 (fp32 src)
    int bkk = tid & 15, bat = tid >> 4;
    uint32_t bswz = (uint32_t)(bkk * 256) + ((uint32_t)(bat ^ (bkk & 7)) << 4);
    size_t wsel = (size_t)e * H_DIM * I_DIM + (size_t)bkk * I_DIM + i0 + (bat >> 1) * 8;
    const float* bwp = ((bat & 1) ? wi1 : wi0) + wsel;

    float c[4][4][4];
#pragma unroll
    for (int i = 0; i < 4; i++)
#pragma unroll
        for (int j = 0; j < 4; j++)
#pragma unroll
            for (int q = 0; q < 4; q++) c[i][j][q] = 0.f;

    float4 pa0, pa1, pb0, pb1;
#define LDG1(K0) do {                                                        \
    if (av) { pa0 = *(const float4*)(axp + (size_t)(K0));                    \
              pa1 = *(const float4*)(axp + (size_t)(K0) + 4); }              \
    else { pa0 = make_float4(0,0,0,0); pa1 = make_float4(0,0,0,0); }         \
    pb0 = *(const float4*)(bwp + (size_t)(K0) * I_DIM);                      \
    pb1 = *(const float4*)(bwp + (size_t)(K0) * I_DIM + 4);                  \
} while (0)
#define STS1(BUF) do {                                                       \
    char* s_ = sm[BUF];                                                      \
    uint4 H_, L_;                                                            \
    split8(pa0, pa1, H_, L_);                                                \
    *(uint4*)(s_ + aswz)         = H_;                                       \
    *(uint4*)(s_ + 4096 + aswz)  = L_;                                       \
    split8(pb0, pb1, H_, L_);                                                \
    *(uint4*)(s_ + 8192  + bswz) = H_;                                       \
    *(uint4*)(s_ + 12288 + bswz) = L_;                                       \
} while (0)

    LDG1(0); STS1(0);
    LDG1(16);
    __syncthreads();

    int arow_l = warpM + (lane & 15);
    uint32_t acol_l = (uint32_t)((lane >> 4) * 16);
    int bk_l = (lane & 7) + ((lane >> 3) & 1) * 8;
    int bnat_l = (warpN >> 3) + ((lane >> 4) & 1);

    const int NC = H_DIM / 16;  // 128
    for (int cc = 0; cc < NC; cc++) {
        if (cc + 1 < NC) {
            STS1((cc + 1) % 3);
            if (cc + 2 < NC) LDG1((cc + 2) * 16);
            __syncthreads();
        }
        COMPUTE_STAGE(sbase + (cc % 3) * 16384);
    }
#undef LDG1
#undef STS1

    // Epilogue: j pairs (0,1),(2,3) = (gate,up); silu in regs, hi/lo fp16 out.
    int gr = lane >> 2, gc = (lane & 3) * 2;
#pragma unroll
    for (int i = 0; i < 4; i++) {
#pragma unroll
        for (int jp = 0; jp < 2; jp++) {
            int jg = jp * 2, ju = jp * 2 + 1;
            int ic = i0 + ((warpN >> 4) + jp) * 8 + gc;
#pragma unroll
            for (int hf = 0; hf < 2; hf++) {
                int slot = m0 + warpM + i * 16 + gr + hf * 8;
                if (slot < ne) {
                    float g0 = c[i][jg][2 * hf], g1 = c[i][jg][2 * hf + 1];
                    float u0 = c[i][ju][2 * hf], u1 = c[i][ju][2 * hf + 1];
                    float a0 = (g0 / (1.f + expf(-g0))) * u0;
                    float a1 = (g1 / (1.f + expf(-g1))) * u1;
                    uint32_t H_, L_;
                    split2(a0, a1, H_, L_);
                    size_t off = ((size_t)e * T_TOK + slot) * I_DIM + ic;
                    *(uint32_t*)(g_acth + off) = H_;
                    *(uint32_t*)(g_actl + off) = L_;
                }
            }
        }
    }
}

// ---------------------------------------------------------------------------
__global__ __launch_bounds__(256)
void k_mlp2(const float* __restrict__ wo, float* __restrict__ out) {
    __shared__ __align__(16) char sm[3][16384];
    int e  = blockIdx.z;
    int ne = g_cnt[e];
    int m0 = blockIdx.x * 128;
    if (m0 >= ne) return;
    int n0 = blockIdx.y * 128;

    int tid = threadIdx.x, lane = tid & 31, wid = tid >> 5;
    int warpM = (wid >> 2) * 64, warpN = (wid & 3) * 32;
    uint32_t sbase = smem_u32(sm);

    // A: pre-split fp16 planes from mlp1
    int ar = tid >> 1;
    uint32_t aswz = (uint32_t)(ar * 32) +
                    (((uint32_t)((tid & 1) * 16)) ^ ((((uint32_t)ar >> 2) & 1) << 4));
    bool av = (m0 + ar) < ne;
    size_t aoff = ((size_t)e * T_TOK + m0 + ar) * I_DIM + (tid & 1) * 8;
    const __half* ah = g_acth + aoff;
    const __half* al = g_actl + aoff;

    // B: wo fp32, split on load
    int bkk = tid & 15, bat = tid >> 4;
    uint32_t bswz = (uint32_t)(bkk * 256) + ((uint32_t)(bat ^ (bkk & 7)) << 4);
    const float* bwp = wo + (size_t)e * I_DIM * H_DIM + (size_t)bkk * H_DIM + n0 + bat * 8;

    float c[4][4][4];
#pragma unroll
    for (int i = 0; i < 4; i++)
#pragma unroll
        for (int j = 0; j < 4; j++)
#pragma unroll
            for (int q = 0; q < 4; q++) c[i][j][q] = 0.f;

    uint4 pah, pal;
    float4 pb0, pb1;
#define LDG2(K0) do {                                                        \
    if (av) { pah = *(const uint4*)(ah + (size_t)(K0));                      \
              pal = *(const uint4*)(al + (size_t)(K0)); }                    \
    else { pah = make_uint4(0,0,0,0); pal = make_uint4(0,0,0,0); }           \
    pb0 = *(const float4*)(bwp + (size_t)(K0) * H_DIM);                      \
    pb1 = *(const float4*)(bwp + (size_t)(K0) * H_DIM + 4);                  \
} while (0)
#define STS2(BUF) do {                                                       \
    char* s_ = sm[BUF];                                                      \
    *(uint4*)(s_ + aswz)         = pah;                                      \
    *(uint4*)(s_ + 4096 + aswz)  = pal;                                      \
    uint4 H_, L_;                                                            \
    split8(pb0, pb1, H_, L_);                                                \
    *(uint4*)(s_ + 8192  + bswz) = H_;                                       \
    *(uint4*)(s_ + 12288 + bswz) = L_;                                       \
} while (0)

    LDG2(0); STS2(0);
    LDG2(16);
    __syncthreads();

    int arow_l = warpM + (lane & 15);
    uint32_t acol_l = (uint32_t)((lane >> 4) * 16);
    int bk_l = (lane & 7) + ((lane >> 3) & 1) * 8;
    int bnat_l = (warpN >> 3) + ((lane >> 4) & 1);

    const int NC = I_DIM / 16;  // 48
    for (int cc = 0; cc < NC; cc++) {
        if (cc + 1 < NC) {
            STS2((cc + 1) % 3);
            if (cc + 2 < NC) LDG2((cc + 2) * 16);
            __syncthreads();
        }
        COMPUTE_STAGE(sbase + (cc % 3) * 16384);
    }
#undef LDG2
#undef STS2

    int gr = lane >> 2, gc = (lane & 3) * 2;
#pragma unroll
    for (int i = 0; i < 4; i++) {
#pragma unroll
        for (int hf = 0; hf < 2; hf++) {
            int r = m0 + warpM + i * 16 + gr + hf * 8;
            if (r < ne) {
                int   t = g_tok[e * T_TOK + r];
                float w = g_wt [e * T_TOK + r];
                float* op = out + (size_t)t * H_DIM + n0 + warpN;
#pragma unroll
                for (int j = 0; j < 4; j++) {
                    atomicAdd(op + j * 8 + gc,     w * c[i][j][2 * hf]);
                    atomicAdd(op + j * 8 + gc + 1, w * c[i][j][2 * hf + 1]);
                }
            }
        }
    }
}

// ---------------------------------------------------------------------------
extern "C" void kernel_launch(void* const* d_in, const int* in_sizes, int n_in,
                              void* d_out, int out_size) {
    const float* x   = (const float*)d_in[0];
    const float* wr  = (const float*)d_in[1];
    const float* wi0 = (const float*)d_in[2];
    const float* wi1 = (const float*)d_in[3];
    const float* wo  = (const float*)d_in[4];
    float* out = (float*)d_out;

    int write_logits = (out_size >= T_TOK * H_DIM + T_TOK * E_NUM) ? 1 : 0;

    cudaMemsetAsync(out, 0, (size_t)T_TOK * H_DIM * sizeof(float));
    k_init<<<1, 32>>>();
    k_router<<<T_TOK / 8, 256>>>(x, wr, out + (size_t)T_TOK * H_DIM, write_logits);

    dim3 g1(T_TOK / 128, I_DIM / 64, E_NUM);   // (32, 12, 8)
    k_mlp1<<<g1, 256>>>(x, wi0, wi1);

    dim3 g2(T_TOK / 128, H_DIM / 128, E_NUM);  // (32, 16, 8)
    k_mlp2<<<g2, 256>>>(wo, out);
}

// round 7
// speedup vs baseline: 1.2593x; 1.0456x over previous
#include <cuda_runtime.h>
#include <cuda_fp16.h>
#include <cstdint>
#include <math.h>

#define T_TOK 4096
#define H_DIM 2048
#define I_DIM 768
#define E_NUM 8

// ---- scratch (device globals; no allocation allowed) ----
__device__ int    g_cnt[E_NUM];
__device__ int    g_tok[E_NUM * T_TOK];
__device__ float  g_wt [E_NUM * T_TOK];
__device__ __half g_acth[(size_t)E_NUM * T_TOK * I_DIM];
__device__ __half g_actl[(size_t)E_NUM * T_TOK * I_DIM];

// ============================ helpers ====================================
__device__ __forceinline__ uint32_t smem_u32(const void* p) {
    uint32_t a;
    asm("{ .reg .u64 t; cvta.to.shared.u64 t, %1; cvt.u32.u64 %0, t; }" : "=r"(a) : "l"(p));
    return a;
}
__device__ __forceinline__ void ldm_x4(uint32_t* r, uint32_t a) {
    asm volatile("ldmatrix.sync.aligned.m8n8.x4.shared.b16 {%0,%1,%2,%3}, [%4];"
                 : "=r"(r[0]), "=r"(r[1]), "=r"(r[2]), "=r"(r[3]) : "r"(a));
}
__device__ __forceinline__ void ldm_x4_t(uint32_t* r, uint32_t a) {
    asm volatile("ldmatrix.sync.aligned.m8n8.x4.trans.shared.b16 {%0,%1,%2,%3}, [%4];"
                 : "=r"(r[0]), "=r"(r[1]), "=r"(r[2]), "=r"(r[3]) : "r"(a));
}
__device__ __forceinline__ void mma16816(float* c, const uint32_t* a, uint32_t b0, uint32_t b1) {
    asm volatile("mma.sync.aligned.m16n8k16.row.col.f32.f16.f16.f32 "
                 "{%0,%1,%2,%3}, {%4,%5,%6,%7}, {%8,%9}, {%0,%1,%2,%3};"
                 : "+f"(c[0]), "+f"(c[1]), "+f"(c[2]), "+f"(c[3])
                 : "r"(a[0]), "r"(a[1]), "r"(a[2]), "r"(a[3]), "r"(b0), "r"(b1));
}
__device__ __forceinline__ void split2(float x, float y, uint32_t& H, uint32_t& L) {
    __half hx = __float2half_rn(x), hy = __float2half_rn(y);
    __half lx = __float2half_rn(x - __half2float(hx));
    __half ly = __float2half_rn(y - __half2float(hy));
    __half2 hh = __halves2half2(hx, hy);
    __half2 ll = __halves2half2(lx, ly);
    H = *(uint32_t*)&hh;
    L = *(uint32_t*)&ll;
}
__device__ __forceinline__ void split8(float4 a, float4 b, uint4& H, uint4& L) {
    split2(a.x, a.y, H.x, L.x);
    split2(a.z, a.w, H.y, L.y);
    split2(b.x, b.y, H.z, L.z);
    split2(b.z, b.w, H.w, L.w);
}

// ---------------------------------------------------------------------------
__global__ void k_init() { if (threadIdx.x < E_NUM) g_cnt[threadIdx.x] = 0; }

// ---------------------------------------------------------------------------
__global__ void k_router(const float* __restrict__ x, const float* __restrict__ wr,
                         float* __restrict__ out_logits, int write_logits) {
    int warp = threadIdx.x >> 5, lane = threadIdx.x & 31;
    int t = blockIdx.x * 8 + warp;
    if (t >= T_TOK) return;
    float acc[E_NUM];
#pragma unroll
    for (int e = 0; e < E_NUM; e++) acc[e] = 0.f;
    const float* xp = x + (size_t)t * H_DIM;
    for (int h = lane; h < H_DIM; h += 32) {
        float xv = xp[h];
        const float* w = wr + (size_t)h * E_NUM;
#pragma unroll
        for (int e = 0; e < E_NUM; e++) acc[e] += xv * w[e];
    }
#pragma unroll
    for (int e = 0; e < E_NUM; e++)
#pragma unroll
        for (int o = 16; o > 0; o >>= 1)
            acc[e] += __shfl_xor_sync(0xffffffffu, acc[e], o);
    if (lane == 0) {
        if (write_logits)
#pragma unroll
            for (int e = 0; e < E_NUM; e++)
                out_logits[(size_t)t * E_NUM + e] = acc[e];
        int i1 = 0;
#pragma unroll
        for (int e = 1; e < E_NUM; e++) if (acc[e] > acc[i1]) i1 = e;
        int i2 = (i1 == 0) ? 1 : 0;
#pragma unroll
        for (int e = 0; e < E_NUM; e++)
            if (e != i1 && acc[e] > acc[i2]) i2 = e;
        float p2 = expf(acc[i2] - acc[i1]);
        float w1 = 1.f / (1.f + p2), w2 = p2 * w1;
        int p;
        p = atomicAdd(&g_cnt[i1], 1);
        g_tok[i1 * T_TOK + p] = t; g_wt[i1 * T_TOK + p] = w1;
        p = atomicAdd(&g_cnt[i2], 1);
        g_tok[i2 * T_TOK + p] = t; g_wt[i2 * T_TOK + p] = w2;
    }
}

// ---------------------------------------------------------------------------
// GEMM geometry: BM=128, BN=256, BK=16, 256 thr, warps 2(M)x4(N), warp 64x64.
// Dynamic smem, 3 stages x 24576B: Ah 4K | Al 4K | Bh 8K | Bl 8K. 1 sync/iter.
// A rows 32B, swizzle off^(((row>>2)&1)<<4); B rows 512B, swizzle ^((k&7)<<4)
// on 16B-unit index. fp16x3: D += Ah*Bh + Ah*Bl + Al*Bh; split at fill.
#define STAGE_B 24576

#define COMPUTE_STAGE(SB0)                                                    \
    do {                                                                      \
        uint32_t Af[4][4], Al_[4][4];                                         \
        _Pragma("unroll")                                                     \
        for (int i = 0; i < 4; i++) {                                         \
            int row = arow_l + i * 16;                                        \
            uint32_t ad = (SB0) + row * 32 +                                  \
                          (acol_l ^ ((((uint32_t)row >> 2) & 1) << 4));       \
            ldm_x4(Af[i], ad);                                                \
            ldm_x4(Al_[i], ad + 4096);                                        \
        }                                                                     \
        _Pragma("unroll")                                                     \
        for (int jj = 0; jj < 4; jj++) {                                      \
            uint32_t Bf[4], Bl_[4];                                           \
            uint32_t nat = (uint32_t)(bnat_l + jj * 2);                       \
            uint32_t bd = (SB0) + 8192 + bk_l * 512 +                         \
                          ((nat ^ ((uint32_t)bk_l & 7)) << 4);                \
            ldm_x4_t(Bf, bd);                                                 \
            ldm_x4_t(Bl_, bd + 8192);                                         \
            _Pragma("unroll")                                                 \
            for (int i = 0; i < 4; i++) {                                     \
                mma16816(c[i][jj * 2],     Af[i],  Bf[0],  Bf[1]);            \
                mma16816(c[i][jj * 2],     Af[i],  Bl_[0], Bl_[1]);           \
                mma16816(c[i][jj * 2],     Al_[i], Bf[0],  Bf[1]);            \
                mma16816(c[i][jj * 2 + 1], Af[i],  Bf[2],  Bf[3]);            \
                mma16816(c[i][jj * 2 + 1], Af[i],  Bl_[2], Bl_[3]);           \
                mma16816(c[i][jj * 2 + 1], Al_[i], Bf[2],  Bf[3]);            \
            }                                                                 \
        }                                                                     \
    } while (0)

// GEMM1: per expert, [Ne,H] x [H, 128 gate + 128 up interleaved by 8] -> act
__global__ __launch_bounds__(256)
void k_mlp1(const float* __restrict__ x,
            const float* __restrict__ wi0, const float* __restrict__ wi1) {
    extern __shared__ __align__(16) char sm[];
    int e  = blockIdx.z;
    int ne = g_cnt[e];
    int m0 = blockIdx.x * 128;
    if (m0 >= ne) return;
    int i0 = blockIdx.y * 128;   // I columns [i0, i0+128)

    int tid = threadIdx.x, lane = tid & 31, wid = tid >> 5;
    int warpM = (wid >> 2) * 64, warpN = (wid & 3) * 64;
    uint32_t sbase = smem_u32(sm);

    // A fill map (gathered token rows, fp32 source)
    int ar = tid >> 1;
    uint32_t aswz = (uint32_t)(ar * 32) +
                    (((uint32_t)((tid & 1) * 16)) ^ ((((uint32_t)ar >> 2) & 1) << 4));
    bool av = (m0 + ar) < ne;
    const float* axp = x;
    if (av) axp = x + (size_t)g_tok[e * T_TOK + m0 + ar] * H_DIM + (tid & 1) * 8;

    // B fill map: nat even -> wi0, odd -> wi1; I col = i0 + (nat>>1)*8.
    // Thread covers rows bkk and bkk+8 of the 16-row stage.
    int bkk = tid >> 5;          // 0..7
    int nat = tid & 31;          // 0..31 (16B unit = n8 block)
    uint32_t bswz = (uint32_t)(bkk * 512) + ((uint32_t)(nat ^ (bkk & 7)) << 4);
    size_t wsel = (size_t)e * H_DIM * I_DIM + (size_t)bkk * I_DIM + i0 + (nat >> 1) * 8;
    const float* bwp = ((nat & 1) ? wi1 : wi0) + wsel;

    float c[4][8][4];
#pragma unroll
    for (int i = 0; i < 4; i++)
#pragma unroll
        for (int j = 0; j < 8; j++)
#pragma unroll
            for (int q = 0; q < 4; q++) c[i][j][q] = 0.f;

    float4 pa0, pa1, pb0a, pb0b, pb1a, pb1b;
#define LDG1(K0) do {                                                        \
    if (av) { pa0 = *(const float4*)(axp + (size_t)(K0));                    \
              pa1 = *(const float4*)(axp + (size_t)(K0) + 4); }              \
    else { pa0 = make_float4(0,0,0,0); pa1 = make_float4(0,0,0,0); }         \
    pb0a = *(const float4*)(bwp + (size_t)(K0) * I_DIM);                     \
    pb0b = *(const float4*)(bwp + (size_t)(K0) * I_DIM + 4);                 \
    pb1a = *(const float4*)(bwp + (size_t)(K0 + 8) * I_DIM);                 \
    pb1b = *(const float4*)(bwp + (size_t)(K0 + 8) * I_DIM + 4);             \
} while (0)
#define STS1(BUF) do {                                                       \
    char* s_ = sm + (BUF) * STAGE_B;                                         \
    uint4 H_, L_;                                                            \
    split8(pa0, pa1, H_, L_);                                                \
    *(uint4*)(s_ + aswz)         = H_;                                       \
    *(uint4*)(s_ + 4096 + aswz)  = L_;                                       \
    split8(pb0a, pb0b, H_, L_);                                              \
    *(uint4*)(s_ + 8192  + bswz) = H_;                                       \
    *(uint4*)(s_ + 16384 + bswz) = L_;                                       \
    split8(pb1a, pb1b, H_, L_);                                              \
    *(uint4*)(s_ + 8192  + 4096 + bswz) = H_;                                \
    *(uint4*)(s_ + 16384 + 4096 + bswz) = L_;                                \
} while (0)

    LDG1(0); STS1(0);
    LDG1(16);
    __syncthreads();

    int arow_l = warpM + (lane & 15);
    uint32_t acol_l = (uint32_t)((lane >> 4) * 16);
    int bk_l = (lane & 7) + ((lane >> 3) & 1) * 8;
    int bnat_l = (warpN >> 3) + ((lane >> 4) & 1);

    const int NC = H_DIM / 16;  // 128
    for (int cc = 0; cc < NC; cc++) {
        if (cc + 1 < NC) {
            STS1((cc + 1) % 3);
            if (cc + 2 < NC) LDG1((cc + 2) * 16);
            __syncthreads();
        }
        COMPUTE_STAGE(sbase + (cc % 3) * STAGE_B);
    }
#undef LDG1
#undef STS1

    // Epilogue: j pairs (2jj, 2jj+1) = (gate, up) for I col i0+((wid&3)*4+jj)*8
    int gr = lane >> 2, gc = (lane & 3) * 2;
#pragma unroll
    for (int i = 0; i < 4; i++) {
#pragma unroll
        for (int jj = 0; jj < 4; jj++) {
            int jg = jj * 2, ju = jj * 2 + 1;
            int ic = i0 + ((wid & 3) * 4 + jj) * 8 + gc;
#pragma unroll
            for (int hf = 0; hf < 2; hf++) {
                int slot = m0 + warpM + i * 16 + gr + hf * 8;
                if (slot < ne) {
                    float g0 = c[i][jg][2 * hf], g1 = c[i][jg][2 * hf + 1];
                    float u0 = c[i][ju][2 * hf], u1 = c[i][ju][2 * hf + 1];
                    float a0 = (g0 / (1.f + expf(-g0))) * u0;
                    float a1 = (g1 / (1.f + expf(-g1))) * u1;
                    uint32_t H_, L_;
                    split2(a0, a1, H_, L_);
                    size_t off = ((size_t)e * T_TOK + slot) * I_DIM + ic;
                    *(uint32_t*)(g_acth + off) = H_;
                    *(uint32_t*)(g_actl + off) = L_;
                }
            }
        }
    }
}

// ---------------------------------------------------------------------------
__global__ __launch_bounds__(256)
void k_mlp2(const float* __restrict__ wo, float* __restrict__ out) {
    extern __shared__ __align__(16) char sm[];
    int e  = blockIdx.z;
    int ne = g_cnt[e];
    int m0 = blockIdx.x * 128;
    if (m0 >= ne) return;
    int n0 = blockIdx.y * 256;

    int tid = threadIdx.x, lane = tid & 31, wid = tid >> 5;
    int warpM = (wid >> 2) * 64, warpN = (wid & 3) * 64;
    uint32_t sbase = smem_u32(sm);

    // A: pre-split fp16 planes from mlp1
    int ar = tid >> 1;
    uint32_t aswz = (uint32_t)(ar * 32) +
                    (((uint32_t)((tid & 1) * 16)) ^ ((((uint32_t)ar >> 2) & 1) << 4));
    bool av = (m0 + ar) < ne;
    size_t aoff = ((size_t)e * T_TOK + m0 + ar) * I_DIM + (tid & 1) * 8;
    const __half* ah = g_acth + aoff;
    const __half* al = g_actl + aoff;

    // B: wo fp32, split on load; rows bkk and bkk+8
    int bkk = tid >> 5;
    int nat = tid & 31;
    uint32_t bswz = (uint32_t)(bkk * 512) + ((uint32_t)(nat ^ (bkk & 7)) << 4);
    const float* bwp = wo + (size_t)e * I_DIM * H_DIM + (size_t)bkk * H_DIM + n0 + nat * 8;

    float c[4][8][4];
#pragma unroll
    for (int i = 0; i < 4; i++)
#pragma unroll
        for (int j = 0; j < 8; j++)
#pragma unroll
            for (int q = 0; q < 4; q++) c[i][j][q] = 0.f;

    uint4 pah, pal;
    float4 pb0a, pb0b, pb1a, pb1b;
#define LDG2(K0) do {                                                        \
    if (av) { pah = *(const uint4*)(ah + (size_t)(K0));                      \
              pal = *(const uint4*)(al + (size_t)(K0)); }                    \
    else { pah = make_uint4(0,0,0,0); pal = make_uint4(0,0,0,0); }           \
    pb0a = *(const float4*)(bwp + (size_t)(K0) * H_DIM);                     \
    pb0b = *(const float4*)(bwp + (size_t)(K0) * H_DIM + 4);                 \
    pb1a = *(const float4*)(bwp + (size_t)(K0 + 8) * H_DIM);                 \
    pb1b = *(const float4*)(bwp + (size_t)(K0 + 8) * H_DIM + 4);             \
} while (0)
#define STS2(BUF) do {                                                       \
    char* s_ = sm + (BUF) * STAGE_B;                                         \
    *(uint4*)(s_ + aswz)         = pah;                                      \
    *(uint4*)(s_ + 4096 + aswz)  = pal;                                      \
    uint4 H_, L_;                                                            \
    split8(pb0a, pb0b, H_, L_);                                              \
    *(uint4*)(s_ + 8192  + bswz) = H_;                                       \
    *(uint4*)(s_ + 16384 + bswz) = L_;                                       \
    split8(pb1a, pb1b, H_, L_);                                              \
    *(uint4*)(s_ + 8192  + 4096 + bswz) = H_;                                \
    *(uint4*)(s_ + 16384 + 4096 + bswz) = L_;                                \
} while (0)

    LDG2(0); STS2(0);
    LDG2(16);
    __syncthreads();

    int arow_l = warpM + (lane & 15);
    uint32_t acol_l = (uint32_t)((lane >> 4) * 16);
    int bk_l = (lane & 7) + ((lane >> 3) & 1) * 8;
    int bnat_l = (warpN >> 3) + ((lane >> 4) & 1);

    const int NC = I_DIM / 16;  // 48
    for (int cc = 0; cc < NC; cc++) {
        if (cc + 1 < NC) {
            STS2((cc + 1) % 3);
            if (cc + 2 < NC) LDG2((cc + 2) * 16);
            __syncthreads();
        }
        COMPUTE_STAGE(sbase + (cc % 3) * STAGE_B);
    }
#undef LDG2
#undef STS2

    int gr = lane >> 2, gc = (lane & 3) * 2;
#pragma unroll
    for (int i = 0; i < 4; i++) {
#pragma unroll
        for (int hf = 0; hf < 2; hf++) {
            int r = m0 + warpM + i * 16 + gr + hf * 8;
            if (r < ne) {
                int   t = g_tok[e * T_TOK + r];
                float w = g_wt [e * T_TOK + r];
                float* op = out + (size_t)t * H_DIM + n0 + warpN;
#pragma unroll
                for (int j = 0; j < 8; j++) {
                    atomicAdd(op + j * 8 + gc,     w * c[i][j][2 * hf]);
                    atomicAdd(op + j * 8 + gc + 1, w * c[i][j][2 * hf + 1]);
                }
            }
        }
    }
}

// ---------------------------------------------------------------------------
extern "C" void kernel_launch(void* const* d_in, const int* in_sizes, int n_in,
                              void* d_out, int out_size) {
    const float* x   = (const float*)d_in[0];
    const float* wr  = (const float*)d_in[1];
    const float* wi0 = (const float*)d_in[2];
    const float* wi1 = (const float*)d_in[3];
    const float* wo  = (const float*)d_in[4];
    float* out = (float*)d_out;

    const int SMEM = 3 * STAGE_B;  // 73728
    cudaFuncSetAttribute(k_mlp1, cudaFuncAttributeMaxDynamicSharedMemorySize, SMEM);
    cudaFuncSetAttribute(k_mlp2, cudaFuncAttributeMaxDynamicSharedMemorySize, SMEM);

    int write_logits = (out_size >= T_TOK * H_DIM + T_TOK * E_NUM) ? 1 : 0;

    cudaMemsetAsync(out, 0, (size_t)T_TOK * H_DIM * sizeof(float));
    k_init<<<1, 32>>>();
    k_router<<<T_TOK / 8, 256>>>(x, wr, out + (size_t)T_TOK * H_DIM, write_logits);

    dim3 g1(T_TOK / 128, I_DIM / 128, E_NUM);   // (32, 6, 8)
    k_mlp1<<<g1, 256, SMEM>>>(x, wi0, wi1);

    dim3 g2(T_TOK / 128, H_DIM / 256, E_NUM);   // (32, 8, 8)
    k_mlp2<<<g2, 256, SMEM>>>(wo, out);
}

// round 8
// speedup vs baseline: 1.3453x; 1.0683x over previous
#include <cuda_runtime.h>
#include <cuda_fp16.h>
#include <cstdint>
#include <math.h>

#define T_TOK 4096
#define H_DIM 2048
#define I_DIM 768
#define E_NUM 8

// ---- scratch (device globals; no allocation allowed) ----
__device__ int    g_cnt[E_NUM];
__device__ int    g_tok[E_NUM * T_TOK];
__device__ float  g_wt [E_NUM * T_TOK];
__device__ __half g_acth[(size_t)E_NUM * T_TOK * I_DIM];
__device__ __half g_actl[(size_t)E_NUM * T_TOK * I_DIM];

// ============================ helpers ====================================
__device__ __forceinline__ uint32_t smem_u32(const void* p) {
    uint32_t a;
    asm("{ .reg .u64 t; cvta.to.shared.u64 t, %1; cvt.u32.u64 %0, t; }" : "=r"(a) : "l"(p));
    return a;
}
__device__ __forceinline__ void ldm_x4(uint32_t* r, uint32_t a) {
    asm volatile("ldmatrix.sync.aligned.m8n8.x4.shared.b16 {%0,%1,%2,%3}, [%4];"
                 : "=r"(r[0]), "=r"(r[1]), "=r"(r[2]), "=r"(r[3]) : "r"(a));
}
__device__ __forceinline__ void ldm_x4_t(uint32_t* r, uint32_t a) {
    asm volatile("ldmatrix.sync.aligned.m8n8.x4.trans.shared.b16 {%0,%1,%2,%3}, [%4];"
                 : "=r"(r[0]), "=r"(r[1]), "=r"(r[2]), "=r"(r[3]) : "r"(a));
}
__device__ __forceinline__ void mma16816(float* c, const uint32_t* a, uint32_t b0, uint32_t b1) {
    asm volatile("mma.sync.aligned.m16n8k16.row.col.f32.f16.f16.f32 "
                 "{%0,%1,%2,%3}, {%4,%5,%6,%7}, {%8,%9}, {%0,%1,%2,%3};"
                 : "+f"(c[0]), "+f"(c[1]), "+f"(c[2]), "+f"(c[3])
                 : "r"(a[0]), "r"(a[1]), "r"(a[2]), "r"(a[3]), "r"(b0), "r"(b1));
}
__device__ __forceinline__ void split2(float x, float y, uint32_t& H, uint32_t& L) {
    __half hx = __float2half_rn(x), hy = __float2half_rn(y);
    __half lx = __float2half_rn(x - __half2float(hx));
    __half ly = __float2half_rn(y - __half2float(hy));
    __half2 hh = __halves2half2(hx, hy);
    __half2 ll = __halves2half2(lx, ly);
    H = *(uint32_t*)&hh;
    L = *(uint32_t*)&ll;
}
__device__ __forceinline__ void split8(float4 a, float4 b, uint4& H, uint4& L) {
    split2(a.x, a.y, H.x, L.x);
    split2(a.z, a.w, H.y, L.y);
    split2(b.x, b.y, H.z, L.z);
    split2(b.z, b.w, H.w, L.w);
}

// ---------------------------------------------------------------------------
__global__ void k_init() { if (threadIdx.x < E_NUM) g_cnt[threadIdx.x] = 0; }

// ---------------------------------------------------------------------------
__global__ void k_router(const float* __restrict__ x, const float* __restrict__ wr,
                         float* __restrict__ out_logits, int write_logits) {
    int warp = threadIdx.x >> 5, lane = threadIdx.x & 31;
    int t = blockIdx.x * 8 + warp;
    if (t >= T_TOK) return;
    float acc[E_NUM];
#pragma unroll
    for (int e = 0; e < E_NUM; e++) acc[e] = 0.f;
    const float* xp = x + (size_t)t * H_DIM;
    for (int h = lane; h < H_DIM; h += 32) {
        float xv = xp[h];
        const float* w = wr + (size_t)h * E_NUM;
#pragma unroll
        for (int e = 0; e < E_NUM; e++) acc[e] += xv * w[e];
    }
#pragma unroll
    for (int e = 0; e < E_NUM; e++)
#pragma unroll
        for (int o = 16; o > 0; o >>= 1)
            acc[e] += __shfl_xor_sync(0xffffffffu, acc[e], o);
    if (lane == 0) {
        if (write_logits)
#pragma unroll
            for (int e = 0; e < E_NUM; e++)
                out_logits[(size_t)t * E_NUM + e] = acc[e];
        int i1 = 0;
#pragma unroll
        for (int e = 1; e < E_NUM; e++) if (acc[e] > acc[i1]) i1 = e;
        int i2 = (i1 == 0) ? 1 : 0;
#pragma unroll
        for (int e = 0; e < E_NUM; e++)
            if (e != i1 && acc[e] > acc[i2]) i2 = e;
        float p2 = expf(acc[i2] - acc[i1]);
        float w1 = 1.f / (1.f + p2), w2 = p2 * w1;
        int p;
        p = atomicAdd(&g_cnt[i1], 1);
        g_tok[i1 * T_TOK + p] = t; g_wt[i1 * T_TOK + p] = w1;
        p = atomicAdd(&g_cnt[i2], 1);
        g_tok[i2 * T_TOK + p] = t; g_wt[i2 * T_TOK + p] = w2;
    }
}

// ---------------------------------------------------------------------------
// GEMM geometry: BM=128, BN=256, BK=16, 512 thr, warps 4(M)x4(N), warp 32x64.
// Dynamic smem, 3 stages x 24576B: Ah 4K | Al 4K | Bh 8K | Bl 8K. 1 sync/iter.
// A rows 32B, swizzle off^(((row>>2)&1)<<4); B rows 512B, swizzle ^((k&7)<<4)
// on 16B-unit index. fp16x3: D += Ah*Bh + Ah*Bl + Al*Bh; split at fill.
#define STAGE_B 24576

#define COMPUTE_STAGE(SB0)                                                    \
    do {                                                                      \
        uint32_t Af[2][4], Al_[2][4];                                         \
        _Pragma("unroll")                                                     \
        for (int i = 0; i < 2; i++) {                                         \
            int row = arow_l + i * 16;                                        \
            uint32_t ad = (SB0) + row * 32 +                                  \
                          (acol_l ^ ((((uint32_t)row >> 2) & 1) << 4));       \
            ldm_x4(Af[i], ad);                                                \
            ldm_x4(Al_[i], ad + 4096);                                        \
        }                                                                     \
        _Pragma("unroll")                                                     \
        for (int jj = 0; jj < 4; jj++) {                                      \
            uint32_t Bf[4], Bl_[4];                                           \
            uint32_t nat = (uint32_t)(bnat_l + jj * 2);                       \
            uint32_t bd = (SB0) + 8192 + bk_l * 512 +                         \
                          ((nat ^ ((uint32_t)bk_l & 7)) << 4);                \
            ldm_x4_t(Bf, bd);                                                 \
            ldm_x4_t(Bl_, bd + 8192);                                         \
            _Pragma("unroll")                                                 \
            for (int i = 0; i < 2; i++) {                                     \
                mma16816(c[i][jj * 2],     Af[i],  Bf[0],  Bf[1]);            \
                mma16816(c[i][jj * 2],     Af[i],  Bl_[0], Bl_[1]);           \
                mma16816(c[i][jj * 2],     Al_[i], Bf[0],  Bf[1]);            \
                mma16816(c[i][jj * 2 + 1], Af[i],  Bf[2],  Bf[3]);            \
                mma16816(c[i][jj * 2 + 1], Af[i],  Bl_[2], Bl_[3]);           \
                mma16816(c[i][jj * 2 + 1], Al_[i], Bf[2],  Bf[3]);            \
            }                                                                 \
        }                                                                     \
    } while (0)

// GEMM1: per expert, [Ne,H] x [H, 128 gate + 128 up interleaved by 8] -> act
__global__ __launch_bounds__(512, 1)
void k_mlp1(const float* __restrict__ x,
            const float* __restrict__ wi0, const float* __restrict__ wi1) {
    extern __shared__ __align__(16) char sm[];
    int e  = blockIdx.z;
    int ne = g_cnt[e];
    int m0 = blockIdx.x * 128;
    if (m0 >= ne) return;
    int i0 = blockIdx.y * 128;   // I columns [i0, i0+128)

    int tid = threadIdx.x, lane = tid & 31, wid = tid >> 5;
    int warpM = (wid & 3) * 32, warpN = (wid >> 2) * 64;
    uint32_t sbase = smem_u32(sm);

    // A fill: threads 0..255, 8 fp32 each (gathered token rows)
    bool afill = tid < 256;
    int ar = tid >> 1;                      // 0..127 (for tid<256)
    uint32_t aswz = (uint32_t)(ar * 32) +
                    (((uint32_t)((tid & 1) * 16)) ^ ((((uint32_t)ar >> 2) & 1) << 4));
    bool av = afill && (m0 + ar) < ne;
    const float* axp = x;
    if (av) axp = x + (size_t)g_tok[e * T_TOK + m0 + ar] * H_DIM + (tid & 1) * 8;

    // B fill: all 512 threads, 8 fp32 each. k row = tid>>5, nat = tid&31.
    // nat even -> wi0, odd -> wi1; I col = i0 + (nat>>1)*8.
    int bkk = tid >> 5;          // 0..15
    int nat = tid & 31;          // 16B unit (n8 block)
    uint32_t bswz = (uint32_t)(bkk * 512) + ((uint32_t)(nat ^ (bkk & 7)) << 4);
    size_t wsel = (size_t)e * H_DIM * I_DIM + (size_t)bkk * I_DIM + i0 + (nat >> 1) * 8;
    const float* bwp = ((nat & 1) ? wi1 : wi0) + wsel;

    float c[2][8][4];
#pragma unroll
    for (int i = 0; i < 2; i++)
#pragma unroll
        for (int j = 0; j < 8; j++)
#pragma unroll
            for (int q = 0; q < 4; q++) c[i][j][q] = 0.f;

    float4 pa0, pa1, pb0, pb1;
#define LDG1(K0) do {                                                        \
    if (av) { pa0 = *(const float4*)(axp + (size_t)(K0));                    \
              pa1 = *(const float4*)(axp + (size_t)(K0) + 4); }              \
    else { pa0 = make_float4(0,0,0,0); pa1 = make_float4(0,0,0,0); }         \
    pb0 = *(const float4*)(bwp + (size_t)(K0) * I_DIM);                      \
    pb1 = *(const float4*)(bwp + (size_t)(K0) * I_DIM + 4);                  \
} while (0)
#define STS1(BUF) do {                                                       \
    char* s_ = sm + (BUF) * STAGE_B;                                         \
    uint4 H_, L_;                                                            \
    if (afill) {                                                             \
        split8(pa0, pa1, H_, L_);                                            \
        *(uint4*)(s_ + aswz)        = H_;                                    \
        *(uint4*)(s_ + 4096 + aswz) = L_;                                    \
    }                                                                        \
    split8(pb0, pb1, H_, L_);                                                \
    *(uint4*)(s_ + 8192  + bswz) = H_;                                       \
    *(uint4*)(s_ + 16384 + bswz) = L_;                                       \
} while (0)

    LDG1(0); STS1(0);
    LDG1(16);
    __syncthreads();

    int arow_l = warpM + (lane & 15);
    uint32_t acol_l = (uint32_t)((lane >> 4) * 16);
    int bk_l = (lane & 7) + ((lane >> 3) & 1) * 8;
    int bnat_l = (warpN >> 3) + ((lane >> 4) & 1);

    const int NC = H_DIM / 16;  // 128
    for (int cc = 0; cc < NC; cc++) {
        if (cc + 1 < NC) {
            STS1((cc + 1) % 3);
            if (cc + 2 < NC) LDG1((cc + 2) * 16);
            __syncthreads();
        }
        COMPUTE_STAGE(sbase + (cc % 3) * STAGE_B);
    }
#undef LDG1
#undef STS1

    // Epilogue: accum pairs (2jj, 2jj+1) = (gate, up); I col = i0 + p*8 + gc.
    int gr = lane >> 2, gc = (lane & 3) * 2;
#pragma unroll
    for (int i = 0; i < 2; i++) {
#pragma unroll
        for (int jj = 0; jj < 4; jj++) {
            int jg = jj * 2, ju = jj * 2 + 1;
            int ic = i0 + ((wid >> 2) * 4 + jj) * 8 + gc;
#pragma unroll
            for (int hf = 0; hf < 2; hf++) {
                int slot = m0 + warpM + i * 16 + gr + hf * 8;
                if (slot < ne) {
                    float g0 = c[i][jg][2 * hf], g1 = c[i][jg][2 * hf + 1];
                    float u0 = c[i][ju][2 * hf], u1 = c[i][ju][2 * hf + 1];
                    float a0 = (g0 / (1.f + expf(-g0))) * u0;
                    float a1 = (g1 / (1.f + expf(-g1))) * u1;
                    uint32_t H_, L_;
                    split2(a0, a1, H_, L_);
                    size_t off = ((size_t)e * T_TOK + slot) * I_DIM + ic;
                    *(uint32_t*)(g_acth + off) = H_;
                    *(uint32_t*)(g_actl + off) = L_;
                }
            }
        }
    }
}

// ---------------------------------------------------------------------------
__global__ __launch_bounds__(512, 1)
void k_mlp2(const float* __restrict__ wo, float* __restrict__ out) {
    extern __shared__ __align__(16) char sm[];
    int e  = blockIdx.z;
    int ne = g_cnt[e];
    int m0 = blockIdx.x * 128;
    if (m0 >= ne) return;
    int n0 = blockIdx.y * 256;

    int tid = threadIdx.x, lane = tid & 31, wid = tid >> 5;
    int warpM = (wid & 3) * 32, warpN = (wid >> 2) * 64;
    uint32_t sbase = smem_u32(sm);

    // A fill: threads 0..255, pre-split fp16 planes from mlp1
    bool afill = tid < 256;
    int ar = tid >> 1;
    uint32_t aswz = (uint32_t)(ar * 32) +
                    (((uint32_t)((tid & 1) * 16)) ^ ((((uint32_t)ar >> 2) & 1) << 4));
    bool av = afill && (m0 + ar) < ne;
    size_t aoff = ((size_t)e * T_TOK + m0 + ar) * I_DIM + (tid & 1) * 8;
    const __half* ah = g_acth + aoff;
    const __half* al = g_actl + aoff;

    // B fill: all 512 threads; wo fp32, split on load
    int bkk = tid >> 5;
    int nat = tid & 31;
    uint32_t bswz = (uint32_t)(bkk * 512) + ((uint32_t)(nat ^ (bkk & 7)) << 4);
    const float* bwp = wo + (size_t)e * I_DIM * H_DIM + (size_t)bkk * H_DIM + n0 + nat * 8;

    float c[2][8][4];
#pragma unroll
    for (int i = 0; i < 2; i++)
#pragma unroll
        for (int j = 0; j < 8; j++)
#pragma unroll
            for (int q = 0; q < 4; q++) c[i][j][q] = 0.f;

    uint4 pah, pal;
    float4 pb0, pb1;
#define LDG2(K0) do {                                                        \
    if (av) { pah = *(const uint4*)(ah + (size_t)(K0));                      \
              pal = *(const uint4*)(al + (size_t)(K0)); }                    \
    else { pah = make_uint4(0,0,0,0); pal = make_uint4(0,0,0,0); }           \
    pb0 = *(const float4*)(bwp + (size_t)(K0) * H_DIM);                      \
    pb1 = *(const float4*)(bwp + (size_t)(K0) * H_DIM + 4);                  \
} while (0)
#define STS2(BUF) do {                                                       \
    char* s_ = sm + (BUF) * STAGE_B;                                         \
    if (afill) {                                                             \
        *(uint4*)(s_ + aswz)        = pah;                                   \
        *(uint4*)(s_ + 4096 + aswz) = pal;                                   \
    }                                                                        \
    uint4 H_, L_;                                                            \
    split8(pb0, pb1, H_, L_);                                                \
    *(uint4*)(s_ + 8192  + bswz) = H_;                                       \
    *(uint4*)(s_ + 16384 + bswz) = L_;                                       \
} while (0)

    LDG2(0); STS2(0);
    LDG2(16);
    __syncthreads();

    int arow_l = warpM + (lane & 15);
    uint32_t acol_l = (uint32_t)((lane >> 4) * 16);
    int bk_l = (lane & 7) + ((lane >> 3) & 1) * 8;
    int bnat_l = (warpN >> 3) + ((lane >> 4) & 1);

    const int NC = I_DIM / 16;  // 48
    for (int cc = 0; cc < NC; cc++) {
        if (cc + 1 < NC) {
            STS2((cc + 1) % 3);
            if (cc + 2 < NC) LDG2((cc + 2) * 16);
            __syncthreads();
        }
        COMPUTE_STAGE(sbase + (cc % 3) * STAGE_B);
    }
#undef LDG2
#undef STS2

    int gr = lane >> 2, gc = (lane & 3) * 2;
#pragma unroll
    for (int i = 0; i < 2; i++) {
#pragma unroll
        for (int hf = 0; hf < 2; hf++) {
            int r = m0 + warpM + i * 16 + gr + hf * 8;
            if (r < ne) {
                int   t = g_tok[e * T_TOK + r];
                float w = g_wt [e * T_TOK + r];
                float* op = out + (size_t)t * H_DIM + n0 + warpN;
#pragma unroll
                for (int j = 0; j < 8; j++) {
                    atomicAdd(op + j * 8 + gc,     w * c[i][j][2 * hf]);
                    atomicAdd(op + j * 8 + gc + 1, w * c[i][j][2 * hf + 1]);
                }
            }
        }
    }
}

// ---------------------------------------------------------------------------
extern "C" void kernel_launch(void* const* d_in, const int* in_sizes, int n_in,
                              void* d_out, int out_size) {
    const float* x   = (const float*)d_in[0];
    const float* wr  = (const float*)d_in[1];
    const float* wi0 = (const float*)d_in[2];
    const float* wi1 = (const float*)d_in[3];
    const float* wo  = (const float*)d_in[4];
    float* out = (float*)d_out;

    const int SMEM = 3 * STAGE_B;  // 73728
    cudaFuncSetAttribute(k_mlp1, cudaFuncAttributeMaxDynamicSharedMemorySize, SMEM);
    cudaFuncSetAttribute(k_mlp2, cudaFuncAttributeMaxDynamicSharedMemorySize, SMEM);

    int write_logits = (out_size >= T_TOK * H_DIM + T_TOK * E_NUM) ? 1 : 0;

    cudaMemsetAsync(out, 0, (size_t)T_TOK * H_DIM * sizeof(float));
    k_init<<<1, 32>>>();
    k_router<<<T_TOK / 8, 256>>>(x, wr, out + (size_t)T_TOK * H_DIM, write_logits);

    dim3 g1(T_TOK / 128, I_DIM / 128, E_NUM);   // (32, 6, 8)
    k_mlp1<<<g1, 512, SMEM>>>(x, wi0, wi1);

    dim3 g2(T_TOK / 128, H_DIM / 256, E_NUM);   // (32, 8, 8)
    k_mlp2<<<g2, 512, SMEM>>>(wo, out);
}

// round 9
// speedup vs baseline: 1.6470x; 1.2242x over previous
#include <cuda_runtime.h>
#include <cuda_fp16.h>
#include <cstdint>
#include <math.h>

#define T_TOK 4096
#define H_DIM 2048
#define I_DIM 768
#define E_NUM 8

// ---- scratch (device globals; no allocation allowed) ----
__device__ int    g_cnt[E_NUM];
__device__ int    g_tok[E_NUM * T_TOK];
__device__ float  g_wt [E_NUM * T_TOK];
__device__ __half g_acth[(size_t)E_NUM * T_TOK * I_DIM];
__device__ __half g_actl[(size_t)E_NUM * T_TOK * I_DIM];

// ============================ helpers ====================================
__device__ __forceinline__ uint32_t smem_u32(const void* p) {
    uint32_t a;
    asm("{ .reg .u64 t; cvta.to.shared.u64 t, %1; cvt.u32.u64 %0, t; }" : "=r"(a) : "l"(p));
    return a;
}
__device__ __forceinline__ void ldm_x4(uint32_t* r, uint32_t a) {
    asm volatile("ldmatrix.sync.aligned.m8n8.x4.shared.b16 {%0,%1,%2,%3}, [%4];"
                 : "=r"(r[0]), "=r"(r[1]), "=r"(r[2]), "=r"(r[3]) : "r"(a));
}
__device__ __forceinline__ void ldm_x4_t(uint32_t* r, uint32_t a) {
    asm volatile("ldmatrix.sync.aligned.m8n8.x4.trans.shared.b16 {%0,%1,%2,%3}, [%4];"
                 : "=r"(r[0]), "=r"(r[1]), "=r"(r[2]), "=r"(r[3]) : "r"(a));
}
__device__ __forceinline__ void mma16816(float* c, const uint32_t* a, uint32_t b0, uint32_t b1) {
    asm volatile("mma.sync.aligned.m16n8k16.row.col.f32.f16.f16.f32 "
                 "{%0,%1,%2,%3}, {%4,%5,%6,%7}, {%8,%9}, {%0,%1,%2,%3};"
                 : "+f"(c[0]), "+f"(c[1]), "+f"(c[2]), "+f"(c[3])
                 : "r"(a[0]), "r"(a[1]), "r"(a[2]), "r"(a[3]), "r"(b0), "r"(b1));
}
__device__ __forceinline__ void split2(float x, float y, uint32_t& H, uint32_t& L) {
    __half hx = __float2half_rn(x), hy = __float2half_rn(y);
    __half lx = __float2half_rn(x - __half2float(hx));
    __half ly = __float2half_rn(y - __half2float(hy));
    __half2 hh = __halves2half2(hx, hy);
    __half2 ll = __halves2half2(lx, ly);
    H = *(uint32_t*)&hh;
    L = *(uint32_t*)&ll;
}
__device__ __forceinline__ void split8(float4 a, float4 b, uint4& H, uint4& L) {
    split2(a.x, a.y, H.x, L.x);
    split2(a.z, a.w, H.y, L.y);
    split2(b.x, b.y, H.z, L.z);
    split2(b.z, b.w, H.w, L.w);
}
// convert 8 fp32 -> 8 fp16 (packed uint4), no residual
__device__ __forceinline__ void cvt8(float4 a, float4 b, uint4& H) {
    __half2 h0 = __floats2half2_rn(a.x, a.y);
    __half2 h1 = __floats2half2_rn(a.z, a.w);
    __half2 h2 = __floats2half2_rn(b.x, b.y);
    __half2 h3 = __floats2half2_rn(b.z, b.w);
    H.x = *(uint32_t*)&h0; H.y = *(uint32_t*)&h1;
    H.z = *(uint32_t*)&h2; H.w = *(uint32_t*)&h3;
}

// ---------------------------------------------------------------------------
__global__ void k_init() { if (threadIdx.x < E_NUM) g_cnt[threadIdx.x] = 0; }

// ---------------------------------------------------------------------------
__global__ void k_router(const float* __restrict__ x, const float* __restrict__ wr,
                         float* __restrict__ out_logits, int write_logits) {
    int warp = threadIdx.x >> 5, lane = threadIdx.x & 31;
    int t = blockIdx.x * 8 + warp;
    if (t >= T_TOK) return;
    float acc[E_NUM];
#pragma unroll
    for (int e = 0; e < E_NUM; e++) acc[e] = 0.f;
    const float* xp = x + (size_t)t * H_DIM;
    for (int h = lane; h < H_DIM; h += 32) {
        float xv = xp[h];
        const float* w = wr + (size_t)h * E_NUM;
#pragma unroll
        for (int e = 0; e < E_NUM; e++) acc[e] += xv * w[e];
    }
#pragma unroll
    for (int e = 0; e < E_NUM; e++)
#pragma unroll
        for (int o = 16; o > 0; o >>= 1)
            acc[e] += __shfl_xor_sync(0xffffffffu, acc[e], o);
    if (lane == 0) {
        if (write_logits)
#pragma unroll
            for (int e = 0; e < E_NUM; e++)
                out_logits[(size_t)t * E_NUM + e] = acc[e];
        int i1 = 0;
#pragma unroll
        for (int e = 1; e < E_NUM; e++) if (acc[e] > acc[i1]) i1 = e;
        int i2 = (i1 == 0) ? 1 : 0;
#pragma unroll
        for (int e = 0; e < E_NUM; e++)
            if (e != i1 && acc[e] > acc[i2]) i2 = e;
        float p2 = expf(acc[i2] - acc[i1]);
        float w1 = 1.f / (1.f + p2), w2 = p2 * w1;
        int p;
        p = atomicAdd(&g_cnt[i1], 1);
        g_tok[i1 * T_TOK + p] = t; g_wt[i1 * T_TOK + p] = w1;
        p = atomicAdd(&g_cnt[i2], 1);
        g_tok[i2 * T_TOK + p] = t; g_wt[i2 * T_TOK + p] = w2;
    }
}

// ---------------------------------------------------------------------------
// GEMM geometry: BM=128, BN=256, BK=16, 512 thr, warps 4(M)x4(N), warp 32x64.
// Static smem, 3 stages x 16384B: Ah 4K | Al 4K | Bh 8K. 1 sync/iter.
// A rows 32B, swizzle off^(((row>>2)&1)<<4); B rows 512B, swizzle ^((k&7)<<4)
// on 16B-unit index. fp16x2: D += Ah*Bh + Al*Bh (B plain fp16; A split).
#define STAGE_B 16384

#define COMPUTE_STAGE(SB0)                                                    \
    do {                                                                      \
        uint32_t Af[2][4], Al_[2][4];                                         \
        _Pragma("unroll")                                                     \
        for (int i = 0; i < 2; i++) {                                         \
            int row = arow_l + i * 16;                                        \
            uint32_t ad = (SB0) + row * 32 +                                  \
                          (acol_l ^ ((((uint32_t)row >> 2) & 1) << 4));       \
            ldm_x4(Af[i], ad);                                                \
            ldm_x4(Al_[i], ad + 4096);                                        \
        }                                                                     \
        _Pragma("unroll")                                                     \
        for (int jj = 0; jj < 4; jj++) {                                      \
            uint32_t Bf[4];                                                   \
            uint32_t nat = (uint32_t)(bnat_l + jj * 2);                       \
            uint32_t bd = (SB0) + 8192 + bk_l * 512 +                         \
                          ((nat ^ ((uint32_t)bk_l & 7)) << 4);                \
            ldm_x4_t(Bf, bd);                                                 \
            _Pragma("unroll")                                                 \
            for (int i = 0; i < 2; i++) {                                     \
                mma16816(c[i][jj * 2],     Af[i],  Bf[0], Bf[1]);             \
                mma16816(c[i][jj * 2],     Al_[i], Bf[0], Bf[1]);             \
                mma16816(c[i][jj * 2 + 1], Af[i],  Bf[2], Bf[3]);             \
                mma16816(c[i][jj * 2 + 1], Al_[i], Bf[2], Bf[3]);             \
            }                                                                 \
        }                                                                     \
    } while (0)

// GEMM1: per expert, [Ne,H] x [H, 128 gate + 128 up interleaved by 8] -> act
__global__ __launch_bounds__(512, 1)
void k_mlp1(const float* __restrict__ x,
            const float* __restrict__ wi0, const float* __restrict__ wi1) {
    __shared__ __align__(16) char sm[3][STAGE_B];
    int e  = blockIdx.z;
    int ne = g_cnt[e];
    int m0 = blockIdx.x * 128;
    if (m0 >= ne) return;
    int i0 = blockIdx.y * 128;   // I columns [i0, i0+128)

    int tid = threadIdx.x, lane = tid & 31, wid = tid >> 5;
    int warpM = (wid & 3) * 32, warpN = (wid >> 2) * 64;
    uint32_t sbase = smem_u32(sm);

    // A fill: threads 0..255, 8 fp32 each (gathered token rows), hi/lo split
    bool afill = tid < 256;
    int ar = tid >> 1;
    uint32_t aswz = (uint32_t)(ar * 32) +
                    (((uint32_t)((tid & 1) * 16)) ^ ((((uint32_t)ar >> 2) & 1) << 4));
    bool av = afill && (m0 + ar) < ne;
    const float* axp = x;
    if (av) axp = x + (size_t)g_tok[e * T_TOK + m0 + ar] * H_DIM + (tid & 1) * 8;

    // B fill: all 512 threads, 8 fp32 -> 8 fp16. k = tid>>5, nat = tid&31.
    // nat even -> wi0, odd -> wi1; I col = i0 + (nat>>1)*8.
    int bkk = tid >> 5;
    int nat = tid & 31;
    uint32_t bswz = (uint32_t)(bkk * 512) + ((uint32_t)(nat ^ (bkk & 7)) << 4);
    size_t wsel = (size_t)e * H_DIM * I_DIM + (size_t)bkk * I_DIM + i0 + (nat >> 1) * 8;
    const float* bwp = ((nat & 1) ? wi1 : wi0) + wsel;

    float c[2][8][4];
#pragma unroll
    for (int i = 0; i < 2; i++)
#pragma unroll
        for (int j = 0; j < 8; j++)
#pragma unroll
            for (int q = 0; q < 4; q++) c[i][j][q] = 0.f;

    float4 pa0, pa1, pb0, pb1;
#define LDG1(K0) do {                                                        \
    if (av) { pa0 = *(const float4*)(axp + (size_t)(K0));                    \
              pa1 = *(const float4*)(axp + (size_t)(K0) + 4); }              \
    else { pa0 = make_float4(0,0,0,0); pa1 = make_float4(0,0,0,0); }         \
    pb0 = *(const float4*)(bwp + (size_t)(K0) * I_DIM);                      \
    pb1 = *(const float4*)(bwp + (size_t)(K0) * I_DIM + 4);                  \
} while (0)
#define STS1(BUF) do {                                                       \
    char* s_ = sm[BUF];                                                      \
    uint4 H_, L_;                                                            \
    if (afill) {                                                             \
        split8(pa0, pa1, H_, L_);                                            \
        *(uint4*)(s_ + aswz)        = H_;                                    \
        *(uint4*)(s_ + 4096 + aswz) = L_;                                    \
    }                                                                        \
    cvt8(pb0, pb1, H_);                                                      \
    *(uint4*)(s_ + 8192 + bswz) = H_;                                        \
} while (0)

    LDG1(0); STS1(0);
    LDG1(16);
    __syncthreads();

    int arow_l = warpM + (lane & 15);
    uint32_t acol_l = (uint32_t)((lane >> 4) * 16);
    int bk_l = (lane & 7) + ((lane >> 3) & 1) * 8;
    int bnat_l = (warpN >> 3) + ((lane >> 4) & 1);

    const int NC = H_DIM / 16;  // 128
    for (int cc = 0; cc < NC; cc++) {
        if (cc + 1 < NC) {
            STS1((cc + 1) % 3);
            if (cc + 2 < NC) LDG1((cc + 2) * 16);
            __syncthreads();
        }
        COMPUTE_STAGE(sbase + (cc % 3) * STAGE_B);
    }
#undef LDG1
#undef STS1

    // Epilogue: accum pairs (2jj, 2jj+1) = (gate, up); silu -> hi/lo planes.
    int gr = lane >> 2, gc = (lane & 3) * 2;
#pragma unroll
    for (int i = 0; i < 2; i++) {
#pragma unroll
        for (int jj = 0; jj < 4; jj++) {
            int jg = jj * 2, ju = jj * 2 + 1;
            int ic = i0 + ((wid >> 2) * 4 + jj) * 8 + gc;
#pragma unroll
            for (int hf = 0; hf < 2; hf++) {
                int slot = m0 + warpM + i * 16 + gr + hf * 8;
                if (slot < ne) {
                    float g0 = c[i][jg][2 * hf], g1 = c[i][jg][2 * hf + 1];
                    float u0 = c[i][ju][2 * hf], u1 = c[i][ju][2 * hf + 1];
                    float a0 = (g0 / (1.f + expf(-g0))) * u0;
                    float a1 = (g1 / (1.f + expf(-g1))) * u1;
                    uint32_t H_, L_;
                    split2(a0, a1, H_, L_);
                    size_t off = ((size_t)e * T_TOK + slot) * I_DIM + ic;
                    *(uint32_t*)(g_acth + off) = H_;
                    *(uint32_t*)(g_actl + off) = L_;
                }
            }
        }
    }
}

// ---------------------------------------------------------------------------
__global__ __launch_bounds__(512, 1)
void k_mlp2(const float* __restrict__ wo, float* __restrict__ out) {
    __shared__ __align__(16) char sm[3][STAGE_B];
    int e  = blockIdx.z;
    int ne = g_cnt[e];
    int m0 = blockIdx.x * 128;
    if (m0 >= ne) return;
    int n0 = blockIdx.y * 256;

    int tid = threadIdx.x, lane = tid & 31, wid = tid >> 5;
    int warpM = (wid & 3) * 32, warpN = (wid >> 2) * 64;
    uint32_t sbase = smem_u32(sm);

    // A fill: threads 0..255, pre-split fp16 planes from mlp1
    bool afill = tid < 256;
    int ar = tid >> 1;
    uint32_t aswz = (uint32_t)(ar * 32) +
                    (((uint32_t)((tid & 1) * 16)) ^ ((((uint32_t)ar >> 2) & 1) << 4));
    bool av = afill && (m0 + ar) < ne;
    size_t aoff = ((size_t)e * T_TOK + m0 + ar) * I_DIM + (tid & 1) * 8;
    const __half* ah = g_acth + aoff;
    const __half* al = g_actl + aoff;

    // B fill: all 512 threads; wo fp32 -> fp16
    int bkk = tid >> 5;
    int nat = tid & 31;
    uint32_t bswz = (uint32_t)(bkk * 512) + ((uint32_t)(nat ^ (bkk & 7)) << 4);
    const float* bwp = wo + (size_t)e * I_DIM * H_DIM + (size_t)bkk * H_DIM + n0 + nat * 8;

    float c[2][8][4];
#pragma unroll
    for (int i = 0; i < 2; i++)
#pragma unroll
        for (int j = 0; j < 8; j++)
#pragma unroll
            for (int q = 0; q < 4; q++) c[i][j][q] = 0.f;

    uint4 pah, pal;
    float4 pb0, pb1;
#define LDG2(K0) do {                                                        \
    if (av) { pah = *(const uint4*)(ah + (size_t)(K0));                      \
              pal = *(const uint4*)(al + (size_t)(K0)); }                    \
    else { pah = make_uint4(0,0,0,0); pal = make_uint4(0,0,0,0); }           \
    pb0 = *(const float4*)(bwp + (size_t)(K0) * H_DIM);                      \
    pb1 = *(const float4*)(bwp + (size_t)(K0) * H_DIM + 4);                  \
} while (0)
#define STS2(BUF) do {                                                       \
    char* s_ = sm[BUF];                                                      \
    if (afill) {                                                             \
        *(uint4*)(s_ + aswz)        = pah;                                   \
        *(uint4*)(s_ + 4096 + aswz) = pal;                                   \
    }                                                                        \
    uint4 H_;                                                                \
    cvt8(pb0, pb1, H_);                                                      \
    *(uint4*)(s_ + 8192 + bswz) = H_;                                        \
} while (0)

    LDG2(0); STS2(0);
    LDG2(16);
    __syncthreads();

    int arow_l = warpM + (lane & 15);
    uint32_t acol_l = (uint32_t)((lane >> 4) * 16);
    int bk_l = (lane & 7) + ((lane >> 3) & 1) * 8;
    int bnat_l = (warpN >> 3) + ((lane >> 4) & 1);

    const int NC = I_DIM / 16;  // 48
    for (int cc = 0; cc < NC; cc++) {
        if (cc + 1 < NC) {
            STS2((cc + 1) % 3);
            if (cc + 2 < NC) LDG2((cc + 2) * 16);
            __syncthreads();
        }
        COMPUTE_STAGE(sbase + (cc % 3) * STAGE_B);
    }
#undef LDG2
#undef STS2

    int gr = lane >> 2, gc = (lane & 3) * 2;
#pragma unroll
    for (int i = 0; i < 2; i++) {
#pragma unroll
        for (int hf = 0; hf < 2; hf++) {
            int r = m0 + warpM + i * 16 + gr + hf * 8;
            if (r < ne) {
                int   t = g_tok[e * T_TOK + r];
                float w = g_wt [e * T_TOK + r];
                float* op = out + (size_t)t * H_DIM + n0 + warpN;
#pragma unroll
                for (int j = 0; j < 8; j++) {
                    atomicAdd(op + j * 8 + gc,     w * c[i][j][2 * hf]);
                    atomicAdd(op + j * 8 + gc + 1, w * c[i][j][2 * hf + 1]);
                }
            }
        }
    }
}

// ---------------------------------------------------------------------------
extern "C" void kernel_launch(void* const* d_in, const int* in_sizes, int n_in,
                              void* d_out, int out_size) {
    const float* x   = (const float*)d_in[0];
    const float* wr  = (const float*)d_in[1];
    const float* wi0 = (const float*)d_in[2];
    const float* wi1 = (const float*)d_in[3];
    const float* wo  = (const float*)d_in[4];
    float* out = (float*)d_out;

    int write_logits = (out_size >= T_TOK * H_DIM + T_TOK * E_NUM) ? 1 : 0;

    cudaMemsetAsync(out, 0, (size_t)T_TOK * H_DIM * sizeof(float));
    k_init<<<1, 32>>>();
    k_router<<<T_TOK / 8, 256>>>(x, wr, out + (size_t)T_TOK * H_DIM, write_logits);

    dim3 g1(T_TOK / 128, I_DIM / 128, E_NUM);   // (32, 6, 8)
    k_mlp1<<<g1, 512>>>(x, wi0, wi1);

    dim3 g2(T_TOK / 128, H_DIM / 256, E_NUM);   // (32, 8, 8)
    k_mlp2<<<g2, 512>>>(wo, out);
}

// round 10
// speedup vs baseline: 1.7010x; 1.0328x over previous
#include <cuda_runtime.h>
#include <cuda_fp16.h>
#include <cstdint>
#include <math.h>

#define T_TOK 4096
#define H_DIM 2048
#define I_DIM 768
#define E_NUM 8

// ---- scratch (device globals; no allocation allowed) ----
__device__ int    g_cnt[E_NUM];
__device__ int    g_tok[E_NUM * T_TOK];
__device__ float  g_wt [E_NUM * T_TOK];
__device__ __half g_acth[(size_t)E_NUM * T_TOK * I_DIM];
__device__ __half g_actl[(size_t)E_NUM * T_TOK * I_DIM];

// ============================ helpers ====================================
__device__ __forceinline__ uint32_t smem_u32(const void* p) {
    uint32_t a;
    asm("{ .reg .u64 t; cvta.to.shared.u64 t, %1; cvt.u32.u64 %0, t; }" : "=r"(a) : "l"(p));
    return a;
}
__device__ __forceinline__ void ldm_x4(uint32_t* r, uint32_t a) {
    asm volatile("ldmatrix.sync.aligned.m8n8.x4.shared.b16 {%0,%1,%2,%3}, [%4];"
                 : "=r"(r[0]), "=r"(r[1]), "=r"(r[2]), "=r"(r[3]) : "r"(a));
}
__device__ __forceinline__ void ldm_x4_t(uint32_t* r, uint32_t a) {
    asm volatile("ldmatrix.sync.aligned.m8n8.x4.trans.shared.b16 {%0,%1,%2,%3}, [%4];"
                 : "=r"(r[0]), "=r"(r[1]), "=r"(r[2]), "=r"(r[3]) : "r"(a));
}
__device__ __forceinline__ void mma16816(float* c, const uint32_t* a, uint32_t b0, uint32_t b1) {
    asm volatile("mma.sync.aligned.m16n8k16.row.col.f32.f16.f16.f32 "
                 "{%0,%1,%2,%3}, {%4,%5,%6,%7}, {%8,%9}, {%0,%1,%2,%3};"
                 : "+f"(c[0]), "+f"(c[1]), "+f"(c[2]), "+f"(c[3])
                 : "r"(a[0]), "r"(a[1]), "r"(a[2]), "r"(a[3]), "r"(b0), "r"(b1));
}
__device__ __forceinline__ void split2(float x, float y, uint32_t& H, uint32_t& L) {
    __half hx = __float2half_rn(x), hy = __float2half_rn(y);
    __half lx = __float2half_rn(x - __half2float(hx));
    __half ly = __float2half_rn(y - __half2float(hy));
    __half2 hh = __halves2half2(hx, hy);
    __half2 ll = __halves2half2(lx, ly);
    H = *(uint32_t*)&hh;
    L = *(uint32_t*)&ll;
}
__device__ __forceinline__ void split8(float4 a, float4 b, uint4& H, uint4& L) {
    split2(a.x, a.y, H.x, L.x);
    split2(a.z, a.w, H.y, L.y);
    split2(b.x, b.y, H.z, L.z);
    split2(b.z, b.w, H.w, L.w);
}
__device__ __forceinline__ void cvt8(float4 a, float4 b, uint4& H) {
    __half2 h0 = __floats2half2_rn(a.x, a.y);
    __half2 h1 = __floats2half2_rn(a.z, a.w);
    __half2 h2 = __floats2half2_rn(b.x, b.y);
    __half2 h3 = __floats2half2_rn(b.z, b.w);
    H.x = *(uint32_t*)&h0; H.y = *(uint32_t*)&h1;
    H.z = *(uint32_t*)&h2; H.w = *(uint32_t*)&h3;
}

// ---------------------------------------------------------------------------
__global__ void k_init() { if (threadIdx.x < E_NUM) g_cnt[threadIdx.x] = 0; }

// ---------------------------------------------------------------------------
__global__ void k_router(const float* __restrict__ x, const float* __restrict__ wr,
                         float* __restrict__ out_logits, int write_logits) {
    int warp = threadIdx.x >> 5, lane = threadIdx.x & 31;
    int t = blockIdx.x * 8 + warp;
    if (t >= T_TOK) return;
    float acc[E_NUM];
#pragma unroll
    for (int e = 0; e < E_NUM; e++) acc[e] = 0.f;
    const float* xp = x + (size_t)t * H_DIM;
    for (int h = lane; h < H_DIM; h += 32) {
        float xv = xp[h];
        const float* w = wr + (size_t)h * E_NUM;
#pragma unroll
        for (int e = 0; e < E_NUM; e++) acc[e] += xv * w[e];
    }
#pragma unroll
    for (int e = 0; e < E_NUM; e++)
#pragma unroll
        for (int o = 16; o > 0; o >>= 1)
            acc[e] += __shfl_xor_sync(0xffffffffu, acc[e], o);
    if (lane == 0) {
        if (write_logits)
#pragma unroll
            for (int e = 0; e < E_NUM; e++)
                out_logits[(size_t)t * E_NUM + e] = acc[e];
        int i1 = 0;
#pragma unroll
        for (int e = 1; e < E_NUM; e++) if (acc[e] > acc[i1]) i1 = e;
        int i2 = (i1 == 0) ? 1 : 0;
#pragma unroll
        for (int e = 0; e < E_NUM; e++)
            if (e != i1 && acc[e] > acc[i2]) i2 = e;
        float p2 = expf(acc[i2] - acc[i1]);
        float w1 = 1.f / (1.f + p2), w2 = p2 * w1;
        int p;
        p = atomicAdd(&g_cnt[i1], 1);
        g_tok[i1 * T_TOK + p] = t; g_wt[i1 * T_TOK + p] = w1;
        p = atomicAdd(&g_cnt[i2], 1);
        g_tok[i2 * T_TOK + p] = t; g_wt[i2 * T_TOK + p] = w2;
    }
}

// ---------------------------------------------------------------------------
// GEMM geometry: BM=128, BN=128, BK=16, 256 thr, warps 4(M)x2(N), warp 32x64.
// 2 CTAs/SM. Static smem, 3 stages x 12288B: Ah 4K | Al 4K | Bh 4K. 1 sync/it.
// A rows 32B, swizzle off^(((row>>2)&1)<<4); B rows 256B, swizzle ^((k&7)<<4)
// on 16B-unit index (16 units/row). fp16x2: D += Ah*Bh + Al*Bh.
#define STAGE_B 12288

#define COMPUTE_STAGE(SB0)                                                    \
    do {                                                                      \
        uint32_t Af[2][4], Al_[2][4];                                         \
        _Pragma("unroll")                                                     \
        for (int i = 0; i < 2; i++) {                                         \
            int row = arow_l + i * 16;                                        \
            uint32_t ad = (SB0) + row * 32 +                                  \
                          (acol_l ^ ((((uint32_t)row >> 2) & 1) << 4));       \
            ldm_x4(Af[i], ad);                                                \
            ldm_x4(Al_[i], ad + 4096);                                        \
        }                                                                     \
        _Pragma("unroll")                                                     \
        for (int jj = 0; jj < 4; jj++) {                                      \
            uint32_t Bf[4];                                                   \
            uint32_t nat = (uint32_t)(bnat_l + jj * 2);                       \
            uint32_t bd = (SB0) + 8192 + bk_l * 256 +                         \
                          ((nat ^ ((uint32_t)bk_l & 7)) << 4);                \
            ldm_x4_t(Bf, bd);                                                 \
            _Pragma("unroll")                                                 \
            for (int i = 0; i < 2; i++) {                                     \
                mma16816(c[i][jj * 2],     Af[i],  Bf[0], Bf[1]);             \
                mma16816(c[i][jj * 2],     Al_[i], Bf[0], Bf[1]);             \
                mma16816(c[i][jj * 2 + 1], Af[i],  Bf[2], Bf[3]);             \
                mma16816(c[i][jj * 2 + 1], Al_[i], Bf[2], Bf[3]);             \
            }                                                                 \
        }                                                                     \
    } while (0)

// GEMM1: per expert, [Ne,H] x [H, 32 gate + 32 up interleaved by 8] -> act
__global__ __launch_bounds__(256, 2)
void k_mlp1(const float* __restrict__ x,
            const float* __restrict__ wi0, const float* __restrict__ wi1) {
    __shared__ __align__(16) char sm[3][STAGE_B];
    int e  = blockIdx.z;
    int ne = g_cnt[e];
    int m0 = blockIdx.x * 128;
    if (m0 >= ne) return;
    int i0 = blockIdx.y * 64;   // I columns [i0, i0+64)

    int tid = threadIdx.x, lane = tid & 31, wid = tid >> 5;
    int warpM = (wid & 3) * 32, warpN = (wid >> 2) * 64;
    uint32_t sbase = smem_u32(sm);

    // A fill: 256 threads, 8 fp32 each (gathered token rows), hi/lo split
    int ar = tid >> 1;
    uint32_t aswz = (uint32_t)(ar * 32) +
                    (((uint32_t)((tid & 1) * 16)) ^ ((((uint32_t)ar >> 2) & 1) << 4));
    bool av = (m0 + ar) < ne;
    const float* axp = x;
    if (av) axp = x + (size_t)g_tok[e * T_TOK + m0 + ar] * H_DIM + (tid & 1) * 8;

    // B fill: 256 threads, 8 fp32 -> 8 fp16. k = tid>>4 (0..15), nat = tid&15.
    // nat even -> wi0, odd -> wi1; I col = i0 + (nat>>1)*8.
    int bkk = tid >> 4;
    int nat = tid & 15;
    uint32_t bswz = (uint32_t)(bkk * 256) + ((uint32_t)(nat ^ (bkk & 7)) << 4);
    size_t wsel = (size_t)e * H_DIM * I_DIM + (size_t)bkk * I_DIM + i0 + (nat >> 1) * 8;
    const float* bwp = ((nat & 1) ? wi1 : wi0) + wsel;

    float c[2][8][4];
#pragma unroll
    for (int i = 0; i < 2; i++)
#pragma unroll
        for (int j = 0; j < 8; j++)
#pragma unroll
            for (int q = 0; q < 4; q++) c[i][j][q] = 0.f;

    float4 pa0, pa1, pb0, pb1;
#define LDG1(K0) do {                                                        \
    if (av) { pa0 = *(const float4*)(axp + (size_t)(K0));                    \
              pa1 = *(const float4*)(axp + (size_t)(K0) + 4); }              \
    else { pa0 = make_float4(0,0,0,0); pa1 = make_float4(0,0,0,0); }         \
    pb0 = *(const float4*)(bwp + (size_t)(K0) * I_DIM);                      \
    pb1 = *(const float4*)(bwp + (size_t)(K0) * I_DIM + 4);                  \
} while (0)
#define STS1(BUF) do {                                                       \
    char* s_ = sm[BUF];                                                      \
    uint4 H_, L_;                                                            \
    split8(pa0, pa1, H_, L_);                                                \
    *(uint4*)(s_ + aswz)        = H_;                                        \
    *(uint4*)(s_ + 4096 + aswz) = L_;                                        \
    cvt8(pb0, pb1, H_);                                                      \
    *(uint4*)(s_ + 8192 + bswz) = H_;                                        \
} while (0)

    LDG1(0); STS1(0);
    LDG1(16);
    __syncthreads();

    int arow_l = warpM + (lane & 15);
    uint32_t acol_l = (uint32_t)((lane >> 4) * 16);
    int bk_l = (lane & 7) + ((lane >> 3) & 1) * 8;
    int bnat_l = (warpN >> 3) + ((lane >> 4) & 1);

    const int NC = H_DIM / 16;  // 128
    for (int cc = 0; cc < NC; cc++) {
        if (cc + 1 < NC) {
            STS1((cc + 1) % 3);
            if (cc + 2 < NC) LDG1((cc + 2) * 16);
            __syncthreads();
        }
        COMPUTE_STAGE(sbase + (cc % 3) * STAGE_B);
    }
#undef LDG1
#undef STS1

    // Epilogue: accum pairs (2jj, 2jj+1) = (gate, up); silu -> hi/lo planes.
    int gr = lane >> 2, gc = (lane & 3) * 2;
#pragma unroll
    for (int i = 0; i < 2; i++) {
#pragma unroll
        for (int jj = 0; jj < 4; jj++) {
            int jg = jj * 2, ju = jj * 2 + 1;
            int ic = i0 + ((wid >> 2) * 4 + jj) * 8 + gc;
#pragma unroll
            for (int hf = 0; hf < 2; hf++) {
                int slot = m0 + warpM + i * 16 + gr + hf * 8;
                if (slot < ne) {
                    float g0 = c[i][jg][2 * hf], g1 = c[i][jg][2 * hf + 1];
                    float u0 = c[i][ju][2 * hf], u1 = c[i][ju][2 * hf + 1];
                    float a0 = (g0 / (1.f + expf(-g0))) * u0;
                    float a1 = (g1 / (1.f + expf(-g1))) * u1;
                    uint32_t H_, L_;
                    split2(a0, a1, H_, L_);
                    size_t off = ((size_t)e * T_TOK + slot) * I_DIM + ic;
                    *(uint32_t*)(g_acth + off) = H_;
                    *(uint32_t*)(g_actl + off) = L_;
                }
            }
        }
    }
}

// ---------------------------------------------------------------------------
__global__ __launch_bounds__(256, 2)
void k_mlp2(const float* __restrict__ wo, float* __restrict__ out) {
    __shared__ __align__(16) char sm[3][STAGE_B];
    int e  = blockIdx.z;
    int ne = g_cnt[e];
    int m0 = blockIdx.x * 128;
    if (m0 >= ne) return;
    int n0 = blockIdx.y * 128;

    int tid = threadIdx.x, lane = tid & 31, wid = tid >> 5;
    int warpM = (wid & 3) * 32, warpN = (wid >> 2) * 64;
    uint32_t sbase = smem_u32(sm);

    // A fill: 256 threads, pre-split fp16 planes from mlp1
    int ar = tid >> 1;
    uint32_t aswz = (uint32_t)(ar * 32) +
                    (((uint32_t)((tid & 1) * 16)) ^ ((((uint32_t)ar >> 2) & 1) << 4));
    bool av = (m0 + ar) < ne;
    size_t aoff = ((size_t)e * T_TOK + m0 + ar) * I_DIM + (tid & 1) * 8;
    const __half* ah = g_acth + aoff;
    const __half* al = g_actl + aoff;

    // B fill: 256 threads; wo fp32 -> fp16. k = tid>>4, nat = tid&15.
    int bkk = tid >> 4;
    int nat = tid & 15;
    uint32_t bswz = (uint32_t)(bkk * 256) + ((uint32_t)(nat ^ (bkk & 7)) << 4);
    const float* bwp = wo + (size_t)e * I_DIM * H_DIM + (size_t)bkk * H_DIM + n0 + nat * 8;

    float c[2][8][4];
#pragma unroll
    for (int i = 0; i < 2; i++)
#pragma unroll
        for (int j = 0; j < 8; j++)
#pragma unroll
            for (int q = 0; q < 4; q++) c[i][j][q] = 0.f;

    uint4 pah, pal;
    float4 pb0, pb1;
#define LDG2(K0) do {                                                        \
    if (av) { pah = *(const uint4*)(ah + (size_t)(K0));                      \
              pal = *(const uint4*)(al + (size_t)(K0)); }                    \
    else { pah = make_uint4(0,0,0,0); pal = make_uint4(0,0,0,0); }           \
    pb0 = *(const float4*)(bwp + (size_t)(K0) * H_DIM);                      \
    pb1 = *(const float4*)(bwp + (size_t)(K0) * H_DIM + 4);                  \
} while (0)
#define STS2(BUF) do {                                                       \
    char* s_ = sm[BUF];                                                      \
    *(uint4*)(s_ + aswz)        = pah;                                       \
    *(uint4*)(s_ + 4096 + aswz) = pal;                                       \
    uint4 H_;                                                                \
    cvt8(pb0, pb1, H_);                                                      \
    *(uint4*)(s_ + 8192 + bswz) = H_;                                        \
} while (0)

    LDG2(0); STS2(0);
    LDG2(16);
    __syncthreads();

    int arow_l = warpM + (lane & 15);
    uint32_t acol_l = (uint32_t)((lane >> 4) * 16);
    int bk_l = (lane & 7) + ((lane >> 3) & 1) * 8;
    int bnat_l = (warpN >> 3) + ((lane >> 4) & 1);

    const int NC = I_DIM / 16;  // 48
    for (int cc = 0; cc < NC; cc++) {
        if (cc + 1 < NC) {
            STS2((cc + 1) % 3);
            if (cc + 2 < NC) LDG2((cc + 2) * 16);
            __syncthreads();
        }
        COMPUTE_STAGE(sbase + (cc % 3) * STAGE_B);
    }
#undef LDG2
#undef STS2

    int gr = lane >> 2, gc = (lane & 3) * 2;
#pragma unroll
    for (int i = 0; i < 2; i++) {
#pragma unroll
        for (int hf = 0; hf < 2; hf++) {
            int r = m0 + warpM + i * 16 + gr + hf * 8;
            if (r < ne) {
                int   t = g_tok[e * T_TOK + r];
                float w = g_wt [e * T_TOK + r];
                float* op = out + (size_t)t * H_DIM + n0 + warpN;
#pragma unroll
                for (int j = 0; j < 8; j++) {
                    atomicAdd(op + j * 8 + gc,     w * c[i][j][2 * hf]);
                    atomicAdd(op + j * 8 + gc + 1, w * c[i][j][2 * hf + 1]);
                }
            }
        }
    }
}

// ---------------------------------------------------------------------------
extern "C" void kernel_launch(void* const* d_in, const int* in_sizes, int n_in,
                              void* d_out, int out_size) {
    const float* x   = (const float*)d_in[0];
    const float* wr  = (const float*)d_in[1];
    const float* wi0 = (const float*)d_in[2];
    const float* wi1 = (const float*)d_in[3];
    const float* wo  = (const float*)d_in[4];
    float* out = (float*)d_out;

    int write_logits = (out_size >= T_TOK * H_DIM + T_TOK * E_NUM) ? 1 : 0;

    cudaMemsetAsync(out, 0, (size_t)T_TOK * H_DIM * sizeof(float));
    k_init<<<1, 32>>>();
    k_router<<<T_TOK / 8, 256>>>(x, wr, out + (size_t)T_TOK * H_DIM, write_logits);

    dim3 g1(T_TOK / 128, I_DIM / 64, E_NUM);    // (32, 12, 8)
    k_mlp1<<<g1, 256>>>(x, wi0, wi1);

    dim3 g2(T_TOK / 128, H_DIM / 128, E_NUM);   // (32, 16, 8)
    k_mlp2<<<g2, 256>>>(wo, out);
}

// round 11
// speedup vs baseline: 2.1675x; 1.2742x over previous
#include <cuda_runtime.h>
#include <cuda_fp16.h>
#include <cstdint>
#include <math.h>

#define T_TOK 4096
#define H_DIM 2048
#define I_DIM 768
#define E_NUM 8

// ---- scratch (device globals; no allocation allowed) ----
__device__ int    g_cnt[E_NUM];
__device__ int    g_tok[E_NUM * T_TOK];
__device__ float  g_wt [E_NUM * T_TOK];
__device__ __half g_acth[(size_t)E_NUM * T_TOK * I_DIM];

// ============================ helpers ====================================
__device__ __forceinline__ uint32_t smem_u32(const void* p) {
    uint32_t a;
    asm("{ .reg .u64 t; cvta.to.shared.u64 t, %1; cvt.u32.u64 %0, t; }" : "=r"(a) : "l"(p));
    return a;
}
__device__ __forceinline__ void ldm_x4(uint32_t* r, uint32_t a) {
    asm volatile("ldmatrix.sync.aligned.m8n8.x4.shared.b16 {%0,%1,%2,%3}, [%4];"
                 : "=r"(r[0]), "=r"(r[1]), "=r"(r[2]), "=r"(r[3]) : "r"(a));
}
__device__ __forceinline__ void ldm_x4_t(uint32_t* r, uint32_t a) {
    asm volatile("ldmatrix.sync.aligned.m8n8.x4.trans.shared.b16 {%0,%1,%2,%3}, [%4];"
                 : "=r"(r[0]), "=r"(r[1]), "=r"(r[2]), "=r"(r[3]) : "r"(a));
}
__device__ __forceinline__ void mma16816(float* c, const uint32_t* a, uint32_t b0, uint32_t b1) {
    asm volatile("mma.sync.aligned.m16n8k16.row.col.f32.f16.f16.f32 "
                 "{%0,%1,%2,%3}, {%4,%5,%6,%7}, {%8,%9}, {%0,%1,%2,%3};"
                 : "+f"(c[0]), "+f"(c[1]), "+f"(c[2]), "+f"(c[3])
                 : "r"(a[0]), "r"(a[1]), "r"(a[2]), "r"(a[3]), "r"(b0), "r"(b1));
}
// convert 8 fp32 -> 8 fp16 (packed uint4)
__device__ __forceinline__ void cvt8(float4 a, float4 b, uint4& H) {
    __half2 h0 = __floats2half2_rn(a.x, a.y);
    __half2 h1 = __floats2half2_rn(a.z, a.w);
    __half2 h2 = __floats2half2_rn(b.x, b.y);
    __half2 h3 = __floats2half2_rn(b.z, b.w);
    H.x = *(uint32_t*)&h0; H.y = *(uint32_t*)&h1;
    H.z = *(uint32_t*)&h2; H.w = *(uint32_t*)&h3;
}

// ---------------------------------------------------------------------------
__global__ void k_init() { if (threadIdx.x < E_NUM) g_cnt[threadIdx.x] = 0; }

// ---------------------------------------------------------------------------
__global__ void k_router(const float* __restrict__ x, const float* __restrict__ wr,
                         float* __restrict__ out_logits, int write_logits) {
    int warp = threadIdx.x >> 5, lane = threadIdx.x & 31;
    int t = blockIdx.x * 8 + warp;
    if (t >= T_TOK) return;
    float acc[E_NUM];
#pragma unroll
    for (int e = 0; e < E_NUM; e++) acc[e] = 0.f;
    const float* xp = x + (size_t)t * H_DIM;
    for (int h = lane; h < H_DIM; h += 32) {
        float xv = xp[h];
        const float* w = wr + (size_t)h * E_NUM;
#pragma unroll
        for (int e = 0; e < E_NUM; e++) acc[e] += xv * w[e];
    }
#pragma unroll
    for (int e = 0; e < E_NUM; e++)
#pragma unroll
        for (int o = 16; o > 0; o >>= 1)
            acc[e] += __shfl_xor_sync(0xffffffffu, acc[e], o);
    if (lane == 0) {
        if (write_logits)
#pragma unroll
            for (int e = 0; e < E_NUM; e++)
                out_logits[(size_t)t * E_NUM + e] = acc[e];
        int i1 = 0;
#pragma unroll
        for (int e = 1; e < E_NUM; e++) if (acc[e] > acc[i1]) i1 = e;
        int i2 = (i1 == 0) ? 1 : 0;
#pragma unroll
        for (int e = 0; e < E_NUM; e++)
            if (e != i1 && acc[e] > acc[i2]) i2 = e;
        float p2 = expf(acc[i2] - acc[i1]);
        float w1 = 1.f / (1.f + p2), w2 = p2 * w1;
        int p;
        p = atomicAdd(&g_cnt[i1], 1);
        g_tok[i1 * T_TOK + p] = t; g_wt[i1 * T_TOK + p] = w1;
        p = atomicAdd(&g_cnt[i2], 1);
        g_tok[i2 * T_TOK + p] = t; g_wt[i2 * T_TOK + p] = w2;
    }
}

// ---------------------------------------------------------------------------
// GEMM geometry: BM=128, BN=256, BK=16, 256 thr, warps 2(M)x4(N), warp 64x64.
// Single-pass fp16 (fp32 accumulate). Static smem, 3 stages x 12288B:
// A 4K | B 8K. 1 sync/iter. A rows 32B, swizzle off^(((row>>2)&1)<<4);
// B rows 512B, swizzle ^((k&7)<<4) on 16B-unit index.
#define STAGE_B 12288

#define COMPUTE_STAGE(SB0)                                                    \
    do {                                                                      \
        uint32_t Af[4][4];                                                    \
        _Pragma("unroll")                                                     \
        for (int i = 0; i < 4; i++) {                                         \
            int row = arow_l + i * 16;                                        \
            uint32_t ad = (SB0) + row * 32 +                                  \
                          (acol_l ^ ((((uint32_t)row >> 2) & 1) << 4));       \
            ldm_x4(Af[i], ad);                                                \
        }                                                                     \
        _Pragma("unroll")                                                     \
        for (int jj = 0; jj < 4; jj++) {                                      \
            uint32_t Bf[4];                                                   \
            uint32_t nat = (uint32_t)(bnat_l + jj * 2);                       \
            uint32_t bd = (SB0) + 4096 + bk_l * 512 +                         \
                          ((nat ^ ((uint32_t)bk_l & 7)) << 4);                \
            ldm_x4_t(Bf, bd);                                                 \
            _Pragma("unroll")                                                 \
            for (int i = 0; i < 4; i++) {                                     \
                mma16816(c[i][jj * 2],     Af[i], Bf[0], Bf[1]);              \
                mma16816(c[i][jj * 2 + 1], Af[i], Bf[2], Bf[3]);              \
            }                                                                 \
        }                                                                     \
    } while (0)

// GEMM1: per expert, [Ne,H] x [H, 128 gate + 128 up interleaved by 8] -> act
__global__ __launch_bounds__(256, 1)
void k_mlp1(const float* __restrict__ x,
            const float* __restrict__ wi0, const float* __restrict__ wi1) {
    __shared__ __align__(16) char sm[3][STAGE_B];
    int e  = blockIdx.z;
    int ne = g_cnt[e];
    int m0 = blockIdx.x * 128;
    if (m0 >= ne) return;
    int i0 = blockIdx.y * 128;   // I columns [i0, i0+128)

    int tid = threadIdx.x, lane = tid & 31, wid = tid >> 5;
    int warpM = (wid >> 2) * 64, warpN = (wid & 3) * 64;
    uint32_t sbase = smem_u32(sm);

    // A fill: 256 threads, 8 fp32 -> 8 fp16 (gathered token rows)
    int ar = tid >> 1;
    uint32_t aswz = (uint32_t)(ar * 32) +
                    (((uint32_t)((tid & 1) * 16)) ^ ((((uint32_t)ar >> 2) & 1) << 4));
    bool av = (m0 + ar) < ne;
    const float* axp = x;
    if (av) axp = x + (size_t)g_tok[e * T_TOK + m0 + ar] * H_DIM + (tid & 1) * 8;

    // B fill: 256 threads, 2 rows x 8 fp32 -> fp16. k rows bkk, bkk+8.
    // nat even -> wi0, odd -> wi1; I col = i0 + (nat>>1)*8.
    int bkk = tid >> 5;          // 0..7
    int nat = tid & 31;          // 16B unit (n8 block)
    uint32_t bswz = (uint32_t)(bkk * 512) + ((uint32_t)(nat ^ (bkk & 7)) << 4);
    size_t wsel = (size_t)e * H_DIM * I_DIM + (size_t)bkk * I_DIM + i0 + (nat >> 1) * 8;
    const float* bwp = ((nat & 1) ? wi1 : wi0) + wsel;

    float c[4][8][4];
#pragma unroll
    for (int i = 0; i < 4; i++)
#pragma unroll
        for (int j = 0; j < 8; j++)
#pragma unroll
            for (int q = 0; q < 4; q++) c[i][j][q] = 0.f;

    float4 pa0, pa1, pb0a, pb0b, pb1a, pb1b;
#define LDG1(K0) do {                                                        \
    if (av) { pa0 = *(const float4*)(axp + (size_t)(K0));                    \
              pa1 = *(const float4*)(axp + (size_t)(K0) + 4); }              \
    else { pa0 = make_float4(0,0,0,0); pa1 = make_float4(0,0,0,0); }         \
    pb0a = *(const float4*)(bwp + (size_t)(K0) * I_DIM);                     \
    pb0b = *(const float4*)(bwp + (size_t)(K0) * I_DIM + 4);                 \
    pb1a = *(const float4*)(bwp + (size_t)(K0 + 8) * I_DIM);                 \
    pb1b = *(const float4*)(bwp + (size_t)(K0 + 8) * I_DIM + 4);             \
} while (0)
#define STS1(BUF) do {                                                       \
    char* s_ = sm[BUF];                                                      \
    uint4 H_;                                                                \
    cvt8(pa0, pa1, H_);                                                      \
    *(uint4*)(s_ + aswz) = H_;                                               \
    cvt8(pb0a, pb0b, H_);                                                    \
    *(uint4*)(s_ + 4096 + bswz) = H_;                                        \
    cvt8(pb1a, pb1b, H_);                                                    \
    *(uint4*)(s_ + 4096 + 4096 + bswz) = H_;                                 \
} while (0)

    LDG1(0); STS1(0);
    LDG1(16);
    __syncthreads();

    int arow_l = warpM + (lane & 15);
    uint32_t acol_l = (uint32_t)((lane >> 4) * 16);
    int bk_l = (lane & 7) + ((lane >> 3) & 1) * 8;
    int bnat_l = (warpN >> 3) + ((lane >> 4) & 1);

    const int NC = H_DIM / 16;  // 128
    for (int cc = 0; cc < NC; cc++) {
        if (cc + 1 < NC) {
            STS1((cc + 1) % 3);
            if (cc + 2 < NC) LDG1((cc + 2) * 16);
            __syncthreads();
        }
        COMPUTE_STAGE(sbase + (cc % 3) * STAGE_B);
    }
#undef LDG1
#undef STS1

    // Epilogue: accum pairs (2jj, 2jj+1) = (gate, up); silu -> fp16 act.
    int gr = lane >> 2, gc = (lane & 3) * 2;
#pragma unroll
    for (int i = 0; i < 4; i++) {
#pragma unroll
        for (int jj = 0; jj < 4; jj++) {
            int jg = jj * 2, ju = jj * 2 + 1;
            int ic = i0 + ((wid & 3) * 4 + jj) * 8 + gc;
#pragma unroll
            for (int hf = 0; hf < 2; hf++) {
                int slot = m0 + warpM + i * 16 + gr + hf * 8;
                if (slot < ne) {
                    float g0 = c[i][jg][2 * hf], g1 = c[i][jg][2 * hf + 1];
                    float u0 = c[i][ju][2 * hf], u1 = c[i][ju][2 * hf + 1];
                    float a0 = (g0 / (1.f + expf(-g0))) * u0;
                    float a1 = (g1 / (1.f + expf(-g1))) * u1;
                    __half2 hh = __floats2half2_rn(a0, a1);
                    size_t off = ((size_t)e * T_TOK + slot) * I_DIM + ic;
                    *(uint32_t*)(g_acth + off) = *(uint32_t*)&hh;
                }
            }
        }
    }
}

// ---------------------------------------------------------------------------
__global__ __launch_bounds__(256, 1)
void k_mlp2(const float* __restrict__ wo, float* __restrict__ out) {
    __shared__ __align__(16) char sm[3][STAGE_B];
    int e  = blockIdx.z;
    int ne = g_cnt[e];
    int m0 = blockIdx.x * 128;
    if (m0 >= ne) return;
    int n0 = blockIdx.y * 256;

    int tid = threadIdx.x, lane = tid & 31, wid = tid >> 5;
    int warpM = (wid >> 2) * 64, warpN = (wid & 3) * 64;
    uint32_t sbase = smem_u32(sm);

    // A fill: 256 threads, fp16 act plane
    int ar = tid >> 1;
    uint32_t aswz = (uint32_t)(ar * 32) +
                    (((uint32_t)((tid & 1) * 16)) ^ ((((uint32_t)ar >> 2) & 1) << 4));
    bool av = (m0 + ar) < ne;
    size_t aoff = ((size_t)e * T_TOK + m0 + ar) * I_DIM + (tid & 1) * 8;
    const __half* ah = g_acth + aoff;

    // B fill: 256 threads, 2 rows x 8 fp32 -> fp16
    int bkk = tid >> 5;
    int nat = tid & 31;
    uint32_t bswz = (uint32_t)(bkk * 512) + ((uint32_t)(nat ^ (bkk & 7)) << 4);
    const float* bwp = wo + (size_t)e * I_DIM * H_DIM + (size_t)bkk * H_DIM + n0 + nat * 8;

    float c[4][8][4];
#pragma unroll
    for (int i = 0; i < 4; i++)
#pragma unroll
        for (int j = 0; j < 8; j++)
#pragma unroll
            for (int q = 0; q < 4; q++) c[i][j][q] = 0.f;

    uint4 pah;
    float4 pb0a, pb0b, pb1a, pb1b;
#define LDG2(K0) do {                                                        \
    if (av) pah = *(const uint4*)(ah + (size_t)(K0));                        \
    else    pah = make_uint4(0,0,0,0);                                       \
    pb0a = *(const float4*)(bwp + (size_t)(K0) * H_DIM);                     \
    pb0b = *(const float4*)(bwp + (size_t)(K0) * H_DIM + 4);                 \
    pb1a = *(const float4*)(bwp + (size_t)(K0 + 8) * H_DIM);                 \
    pb1b = *(const float4*)(bwp + (size_t)(K0 + 8) * H_DIM + 4);             \
} while (0)
#define STS2(BUF) do {                                                       \
    char* s_ = sm[BUF];                                                      \
    *(uint4*)(s_ + aswz) = pah;                                              \
    uint4 H_;                                                                \
    cvt8(pb0a, pb0b, H_);                                                    \
    *(uint4*)(s_ + 4096 + bswz) = H_;                                        \
    cvt8(pb1a, pb1b, H_);                                                    \
    *(uint4*)(s_ + 4096 + 4096 + bswz) = H_;                                 \
} while (0)

    LDG2(0); STS2(0);
    LDG2(16);
    __syncthreads();

    int arow_l = warpM + (lane & 15);
    uint32_t acol_l = (uint32_t)((lane >> 4) * 16);
    int bk_l = (lane & 7) + ((lane >> 3) & 1) * 8;
    int bnat_l = (warpN >> 3) + ((lane >> 4) & 1);

    const int NC = I_DIM / 16;  // 48
    for (int cc = 0; cc < NC; cc++) {
        if (cc + 1 < NC) {
            STS2((cc + 1) % 3);
            if (cc + 2 < NC) LDG2((cc + 2) * 16);
            __syncthreads();
        }
        COMPUTE_STAGE(sbase + (cc % 3) * STAGE_B);
    }
#undef LDG2
#undef STS2

    int gr = lane >> 2, gc = (lane & 3) * 2;
#pragma unroll
    for (int i = 0; i < 4; i++) {
#pragma unroll
        for (int hf = 0; hf < 2; hf++) {
            int r = m0 + warpM + i * 16 + gr + hf * 8;
            if (r < ne) {
                int   t = g_tok[e * T_TOK + r];
                float w = g_wt [e * T_TOK + r];
                float* op = out + (size_t)t * H_DIM + n0 + warpN;
#pragma unroll
                for (int j = 0; j < 8; j++) {
                    atomicAdd(op + j * 8 + gc,     w * c[i][j][2 * hf]);
                    atomicAdd(op + j * 8 + gc + 1, w * c[i][j][2 * hf + 1]);
                }
            }
        }
    }
}

// ---------------------------------------------------------------------------
extern "C" void kernel_launch(void* const* d_in, const int* in_sizes, int n_in,
                              void* d_out, int out_size) {
    const float* x   = (const float*)d_in[0];
    const float* wr  = (const float*)d_in[1];
    const float* wi0 = (const float*)d_in[2];
    const float* wi1 = (const float*)d_in[3];
    const float* wo  = (const float*)d_in[4];
    float* out = (float*)d_out;

    int write_logits = (out_size >= T_TOK * H_DIM + T_TOK * E_NUM) ? 1 : 0;

    cudaMemsetAsync(out, 0, (size_t)T_TOK * H_DIM * sizeof(float));
    k_init<<<1, 32>>>();
    k_router<<<T_TOK / 8, 256>>>(x, wr, out + (size_t)T_TOK * H_DIM, write_logits);

    dim3 g1(T_TOK / 128, I_DIM / 128, E_NUM);   // (32, 6, 8)
    k_mlp1<<<g1, 256>>>(x, wi0, wi1);

    dim3 g2(T_TOK / 128, H_DIM / 256, E_NUM);   // (32, 8, 8)
    k_mlp2<<<g2, 256>>>(wo, out);
}